// round 11
// baseline (speedup 1.0000x reference)
#include <cuda_runtime.h>
#include <cuda_fp16.h>
#include <mma.h>
#include <math.h>

using namespace nvcuda;

#define NN   50000
#define NNP  50048           // padded to multiple of 64
#define EE   800000
#define CSRP (EE + 4*NN)     // CSR capacity with per-row pad-to-4
#define INF_ 128
#define H    8
#define HIDD 32
#define OUTD 16
#define C1   (H*HIDD)   // 256
#define C2   (H*OUTD)   // 128

// ---------------- scratch (device globals, zero-initialized) ----------------
__device__ __half g_x16  [(size_t)NNP * INF_];
__device__ __half g_W1_16[INF_ * C1];
__device__ __half g_W2_16[C1 * C2];
__device__ __half g_feat1[(size_t)NNP * C1];   // row NN stays zero (dummy)
__device__ __half g_agg1 [(size_t)NNP * C1];
__device__ __half g_feat2[(size_t)NNP * C2];   // row NN stays zero (dummy)
__device__ float  g_el   [(NN + 1) * H];       // el[NN][*] = -1e30 (dummy)
__device__ float  g_er   [NN * H];
__device__ int    g_csr  [CSRP];
__device__ int    g_rowstart[NN + 1];
__device__ int    g_cnt  [NN];                 // histogram (zeroed by k_scan for replay)
__device__ int    g_cur  [NN];                 // scatter cursor

// ---- merged: dst histogram + fp16 converts + csr dummy fill + dummy el -----
// g_cnt is 0 on entry: static zero-init on the first run; k_scan re-zeroes it
// after consuming it, keeping every graph replay identical.
__global__ void k_hist_convert(const int* __restrict__ dst, const float* __restrict__ x,
                               const float* __restrict__ W1, const float* __restrict__ W2) {
    int i = blockIdx.x * blockDim.x + threadIdx.x;
    if (i < NN * INF_) g_x16[i] = __float2half_rn(x[i]);
    if (i < INF_ * C1) g_W1_16[i] = __float2half_rn(W1[i]);
    if (i < C1 * C2)   g_W2_16[i] = __float2half_rn(W2[i]);
    if (i < CSRP)      g_csr[i] = NN;              // dummy src (zero weight)
    if (i < H)         g_el[NN * H + i] = -1e30f;  // dummy logit -> exp = 0
    if (i < EE)        atomicAdd(&g_cnt[dst[i]], 1);
}

// exclusive scan of counts padded to multiples of 4; zeroes g_cnt for replay
__global__ void k_scan() {
    const int T = 1024;
    const int CH = (NN + T - 1) / T;
    int t = threadIdx.x;
    int base = t * CH;
    int s = 0;
#pragma unroll 4
    for (int i = 0; i < CH; i++) {
        int idx = base + i;
        if (idx < NN) s += (g_cnt[idx] + 3) & ~3;
    }
    __shared__ int sh[T];
    sh[t] = s;
    __syncthreads();
    for (int off = 1; off < T; off <<= 1) {
        int v = (t >= off) ? sh[t - off] : 0;
        __syncthreads();
        sh[t] += v;
        __syncthreads();
    }
    int run = sh[t] - s;
    for (int i = 0; i < CH; i++) {
        int idx = base + i;
        if (idx < NN) {
            int pc = (g_cnt[idx] + 3) & ~3;
            g_rowstart[idx] = run;
            g_cur[idx] = run;      // scatter cursor
            g_cnt[idx] = 0;        // ready for next replay
            run += pc;
        }
    }
    if (t == T - 1) g_rowstart[NN] = run;
}

__global__ void k_scatter(const int* __restrict__ src, const int* __restrict__ dst) {
    int e = blockIdx.x * blockDim.x + threadIdx.x;
    if (e >= EE) return;
    int p = atomicAdd(&g_cur[dst[e]], 1);
    g_csr[p] = src[e];
}

// ---------------- tensor-core GEMM + attention epilogue ----------------------
template<int K, int NC, int D>
__global__ void gemm_att_wmma(const __half* __restrict__ A, const __half* __restrict__ Wm,
                              const float* __restrict__ al, const float* __restrict__ ar,
                              __half* __restrict__ feat, float* __restrict__ el,
                              float* __restrict__ er, int n)
{
    extern __shared__ float sm[];    // 64 * NC floats
    constexpr int NSPAN = NC / 2;
    constexpr int NFRAG = NSPAN / 16;

    int wid = threadIdx.x >> 5;
    int warp_m = wid & 3;
    int warp_n = wid >> 2;
    int m0 = blockIdx.x * 64 + warp_m * 16;

    wmma::fragment<wmma::accumulator, 16, 16, 16, float> c[NFRAG];
#pragma unroll
    for (int f = 0; f < NFRAG; f++) wmma::fill_fragment(c[f], 0.f);

    for (int k = 0; k < K; k += 16) {
        wmma::fragment<wmma::matrix_a, 16, 16, 16, __half, wmma::row_major> a;
        wmma::load_matrix_sync(a, A + (size_t)m0 * K + k, K);
#pragma unroll
        for (int f = 0; f < NFRAG; f++) {
            wmma::fragment<wmma::matrix_b, 16, 16, 16, __half, wmma::row_major> b;
            wmma::load_matrix_sync(b, Wm + (size_t)k * NC + warp_n * NSPAN + f * 16, NC);
            wmma::mma_sync(c[f], a, b, c[f]);
        }
    }

#pragma unroll
    for (int f = 0; f < NFRAG; f++)
        wmma::store_matrix_sync(sm + warp_m * 16 * NC + warp_n * NSPAN + f * 16,
                                c[f], NC, wmma::mem_row_major);
    __syncthreads();

    constexpr int RPT = NC / 4;
    int j = threadIdx.x % NC;
    int r0 = (threadIdx.x / NC) * RPT;
    float alj = al[j], arj = ar[j];
    int head = j / D;
    for (int r = r0; r < r0 + RPT; r++) {
        int row = blockIdx.x * 64 + r;
        float v = sm[r * NC + j];
        bool valid = row < n;
        if (valid) feat[(size_t)row * NC + j] = __float2half_rn(v);
        float ev = v * alj;
        float rv = v * arj;
#pragma unroll
        for (int off = D / 2; off > 0; off >>= 1) {
            ev += __shfl_xor_sync(0xffffffffu, ev, off);
            rv += __shfl_xor_sync(0xffffffffu, rv, off);
        }
        if ((j % D) == 0 && valid) {
            el[row * H + head] = ev;
            er[row * H + head] = rv;
        }
    }
}

// ---------------- fused per-node softmax + aggregate (single pass) ----------
// One warp per dst node. CSR rows padded to multiples of 4 (dummy index NN:
// weight 0, zero feat row) -> single aligned int4 index load, no tail loop.
template<int DT, bool ELU, bool FINAL>
__global__ void node_aggregate(const __half* __restrict__ feat,
                               const float* __restrict__ el,
                               const float* __restrict__ er,
                               const float* __restrict__ bias,
                               void* __restrict__ outp)
{
    int d = blockIdx.x * (blockDim.x >> 5) + (threadIdx.x >> 5);
    if (d >= NN) return;
    int lane = threadIdx.x & 31;
    int head = lane >> 2;
    constexpr int V = DT / 32;        // 8 or 4
    constexpr int NH2 = V / 2;        // 4 or 2

    int beg = g_rowstart[d], end = g_rowstart[d + 1];

    float sum = 0.f;
    float acc[V];
#pragma unroll
    for (int k = 0; k < V; k++) acc[k] = 0.f;

    float erv = (beg < end) ? er[d * H + head] : 0.f;

    for (int i = beg; i < end; i += 4) {
        int4 sv = *(const int4*)(g_csr + i);     // aligned: beg % 4 == 0
        int s0 = sv.x, s1 = sv.y, s2 = sv.z, s3 = sv.w;
        float l0 = el[s0 * H + head];
        float l1 = el[s1 * H + head];
        float l2 = el[s2 * H + head];
        float l3 = el[s3 * H + head];
        __half2 v0[NH2], v1[NH2], v2[NH2], v3[NH2];
        if (V == 8) {
            *(uint4*)v0 = *(const uint4*)((const __half2*)(feat + (size_t)s0 * DT) + lane * NH2);
            *(uint4*)v1 = *(const uint4*)((const __half2*)(feat + (size_t)s1 * DT) + lane * NH2);
            *(uint4*)v2 = *(const uint4*)((const __half2*)(feat + (size_t)s2 * DT) + lane * NH2);
            *(uint4*)v3 = *(const uint4*)((const __half2*)(feat + (size_t)s3 * DT) + lane * NH2);
        } else {
            *(uint2*)v0 = *(const uint2*)((const __half2*)(feat + (size_t)s0 * DT) + lane * NH2);
            *(uint2*)v1 = *(const uint2*)((const __half2*)(feat + (size_t)s1 * DT) + lane * NH2);
            *(uint2*)v2 = *(const uint2*)((const __half2*)(feat + (size_t)s2 * DT) + lane * NH2);
            *(uint2*)v3 = *(const uint2*)((const __half2*)(feat + (size_t)s3 * DT) + lane * NH2);
        }
        l0 += erv; l1 += erv; l2 += erv; l3 += erv;
        l0 = l0 > 0.f ? l0 : 0.2f * l0;
        l1 = l1 > 0.f ? l1 : 0.2f * l1;
        l2 = l2 > 0.f ? l2 : 0.2f * l2;
        l3 = l3 > 0.f ? l3 : 0.2f * l3;
        float w0 = __expf(l0), w1 = __expf(l1), w2 = __expf(l2), w3 = __expf(l3);
        sum += (w0 + w1) + (w2 + w3);
#pragma unroll
        for (int k = 0; k < NH2; k++) {
            float2 a0 = __half22float2(v0[k]);
            float2 a1 = __half22float2(v1[k]);
            float2 a2 = __half22float2(v2[k]);
            float2 a3 = __half22float2(v3[k]);
            acc[k*2+0] += w0*a0.x + w1*a1.x + w2*a2.x + w3*a3.x;
            acc[k*2+1] += w0*a0.y + w1*a1.y + w2*a2.y + w3*a3.y;
        }
    }

    float inv = (beg < end) ? 1.f / sum : 0.f;

    float vals[V];
#pragma unroll
    for (int k = 0; k < V; k++) {
        float v = acc[k] * inv + bias[lane * V + k];
        vals[k] = ELU ? (v > 0.f ? v : expm1f(v)) : v;
    }

    if (!FINAL) {
        __half2 hv[NH2];
#pragma unroll
        for (int k = 0; k < NH2; k++)
            hv[k] = __floats2half2_rn(vals[k*2+0], vals[k*2+1]);
        __half* op = (__half*)outp + (size_t)d * DT + lane * V;
        if (V == 8) *(uint4*)op = *(uint4*)hv;
        else        *(uint2*)op = *(uint2*)hv;
    } else {
        // DT=128, V=4: head-mean via xor-reduce over head lanes
#pragma unroll
        for (int off = 4; off <= 16; off <<= 1) {
#pragma unroll
            for (int k = 0; k < V; k++)
                vals[k] += __shfl_xor_sync(0xffffffffu, vals[k], off);
        }
        if (lane < 4) {
            float4 o = make_float4(vals[0] * 0.125f, vals[1] * 0.125f,
                                   vals[2] * 0.125f, vals[3] * 0.125f);
            ((float4*)((float*)outp + (size_t)d * OUTD))[lane] = o;
        }
    }
}

// ---------------- launch ----------------------------------------------------
extern "C" void kernel_launch(void* const* d_in, const int* in_sizes, int n_in,
                              void* d_out, int out_size)
{
    const float* x   = (const float*)d_in[0];
    const float* W1  = (const float*)d_in[1];
    const float* al1 = (const float*)d_in[2];
    const float* ar1 = (const float*)d_in[3];
    const float* b1  = (const float*)d_in[4];
    const float* W2  = (const float*)d_in[5];
    const float* al2 = (const float*)d_in[6];
    const float* ar2 = (const float*)d_in[7];
    const float* b2  = (const float*)d_in[8];
    const int*   src = (const int*)d_in[9];
    const int*   dst = (const int*)d_in[10];
    float* out = (float*)d_out;

    __half *x16, *W1h, *W2h, *feat1, *agg1, *feat2;
    float *el, *er;
    cudaGetSymbolAddress((void**)&x16,   g_x16);
    cudaGetSymbolAddress((void**)&W1h,   g_W1_16);
    cudaGetSymbolAddress((void**)&W2h,   g_W2_16);
    cudaGetSymbolAddress((void**)&feat1, g_feat1);
    cudaGetSymbolAddress((void**)&agg1,  g_agg1);
    cudaGetSymbolAddress((void**)&feat2, g_feat2);
    cudaGetSymbolAddress((void**)&el,    g_el);
    cudaGetSymbolAddress((void**)&er,    g_er);

    static bool attrDone = false;
    if (!attrDone) {
        cudaFuncSetAttribute((const void*)gemm_att_wmma<INF_, C1, HIDD>,
                             cudaFuncAttributeMaxDynamicSharedMemorySize, 64 * C1 * 4);
        cudaFuncSetAttribute((const void*)gemm_att_wmma<C1, C2, OUTD>,
                             cudaFuncAttributeMaxDynamicSharedMemorySize, 64 * C2 * 4);
        attrDone = true;
    }

    const int eBlocks    = (EE + 255) / 256;
    const int gemmBlocks = NNP / 64;
    const int nodeBlocks = (NN + 7) / 8;

    // 1: converts + dst histogram + csr dummy fill + dummy el (one grid)
    k_hist_convert<<<(NN*INF_ + 255)/256, 256>>>(dst, x, W1, W2);
    // 2: scan (pads rows to 4, sets cursor, re-zeroes histogram for replay)
    k_scan<<<1, 1024>>>();
    // 3: scatter
    k_scatter<<<eBlocks, 256>>>(src, dst);
    // 4: layer-1 GEMM  <-- profiled slot
    gemm_att_wmma<INF_, C1, HIDD><<<gemmBlocks, 256, 64*C1*4>>>(x16, W1h, al1, ar1,
                                                                feat1, el, er, NN);
    // 5: layer-1 aggregate
    node_aggregate<C1, true, false><<<nodeBlocks, 256>>>(feat1, el, er, b1, agg1);
    // 6: layer-2 GEMM
    gemm_att_wmma<C1, C2, OUTD><<<gemmBlocks, 256, 64*C2*4>>>(agg1, W2h, al2, ar2,
                                                              feat2, el, er, NN);
    // 7: layer-2 aggregate + head-mean
    node_aggregate<C2, false, true><<<nodeBlocks, 256>>>(feat2, el, er, b2, out);
}

// round 12
// speedup vs baseline: 1.3546x; 1.3546x over previous
#include <cuda_runtime.h>
#include <cuda_fp16.h>
#include <mma.h>
#include <math.h>

using namespace nvcuda;

#define NN   50000
#define NNP  50048           // padded to multiple of 64
#define EE   800000
#define CSRP (EE + 4*NN)     // CSR capacity with per-row pad-to-4
#define INF_ 128
#define H    8
#define HIDD 32
#define OUTD 16
#define C1   (H*HIDD)   // 256
#define C2   (H*OUTD)   // 128

// ---------------- scratch (device globals, zero-initialized) ----------------
__device__ __half g_x16  [(size_t)NNP * INF_];
__device__ __half g_W1_16[INF_ * C1];
__device__ __half g_W2_16[C1 * C2];
__device__ __half g_feat1[(size_t)NNP * C1];   // row NN stays zero (dummy)
__device__ __half g_agg1 [(size_t)NNP * C1];
__device__ __half g_feat2[(size_t)NNP * C2];   // row NN stays zero (dummy)
__device__ float  g_el   [(NN + 1) * H];       // el[NN][*] = -1e30 (dummy)
__device__ float  g_er   [NN * H];
__device__ int    g_csr  [CSRP];
__device__ int    g_rowstart[NN + 1];
__device__ int    g_cnt  [NN];

// ---------------- merged: converts + zero cnt + csr dummy fill + dummy el ----
__global__ void k_convert(const float* __restrict__ x, const float* __restrict__ W1,
                          const float* __restrict__ W2) {
    int i = blockIdx.x * blockDim.x + threadIdx.x;
    if (i < NN * INF_) g_x16[i] = __float2half_rn(x[i]);
    if (i < INF_ * C1) g_W1_16[i] = __float2half_rn(W1[i]);
    if (i < C1 * C2)   g_W2_16[i] = __float2half_rn(W2[i]);
    if (i < NN)        g_cnt[i] = 0;
    if (i < CSRP)      g_csr[i] = NN;              // dummy src (zero weight)
    if (i < H)         g_el[NN * H + i] = -1e30f;  // dummy logit -> exp = 0
}

__global__ void k_hist(const int* __restrict__ dst) {
    int e = blockIdx.x * blockDim.x + threadIdx.x;
    if (e < EE) atomicAdd(&g_cnt[dst[e]], 1);
}

// exclusive scan of counts padded to multiples of 4
__global__ void k_scan() {
    const int T = 1024;
    const int CH = (NN + T - 1) / T;
    int t = threadIdx.x;
    int base = t * CH;
    int s = 0;
#pragma unroll 4
    for (int i = 0; i < CH; i++) {
        int idx = base + i;
        if (idx < NN) s += (g_cnt[idx] + 3) & ~3;
    }
    __shared__ int sh[T];
    sh[t] = s;
    __syncthreads();
    for (int off = 1; off < T; off <<= 1) {
        int v = (t >= off) ? sh[t - off] : 0;
        __syncthreads();
        sh[t] += v;
        __syncthreads();
    }
    int run = sh[t] - s;
    for (int i = 0; i < CH; i++) {
        int idx = base + i;
        if (idx < NN) {
            int pc = (g_cnt[idx] + 3) & ~3;
            g_rowstart[idx] = run;
            g_cnt[idx] = run;      // scatter cursor
            run += pc;
        }
    }
    if (t == T - 1) g_rowstart[NN] = run;
}

__global__ void k_scatter(const int* __restrict__ src, const int* __restrict__ dst) {
    int e = blockIdx.x * blockDim.x + threadIdx.x;
    if (e >= EE) return;
    int p = atomicAdd(&g_cnt[dst[e]], 1);
    g_csr[p] = src[e];
}

// ---------------- smem-tiled tensor-core GEMM + attention epilogue -----------
// W [K,NC] staged whole in smem (row stride NC+8 halves to stagger banks);
// A 64-row tile staged in smem (row stride K+8). All wmma fragment loads hit
// smem. Epilogue float tile reuses the same smem region.
template<int K, int NC, int D>
__global__ void gemm_att_wmma(const __half* __restrict__ A, const __half* __restrict__ Wm,
                              const float* __restrict__ al, const float* __restrict__ ar,
                              __half* __restrict__ feat, float* __restrict__ el,
                              float* __restrict__ er, int n)
{
    extern __shared__ char smraw[];
    constexpr int WS = NC + 8;            // W smem row stride (halves)
    constexpr int AS = K + 8;             // A smem row stride (halves)
    __half* sW = (__half*)smraw;                       // K * WS halves
    __half* sA = (__half*)smraw + (size_t)K * WS;      // 64 * AS halves
    float*  ep = (float*)smraw;                        // epilogue reuse: 64*NC floats

    constexpr int NSPAN = NC / 2;
    constexpr int NFRAG = NSPAN / 16;

    int tid = threadIdx.x;
    int wid = tid >> 5;
    int warp_m = wid & 3;
    int warp_n = wid >> 2;
    int m0 = blockIdx.x * 64;

    // cooperative W load: K*NC/8 uint4
    {
        const uint4* wg = (const uint4*)Wm;
        constexpr int ROW4 = NC / 8;             // uint4 per row
        for (int idx = tid; idx < K * ROW4; idx += 256) {
            int row = idx / ROW4, c = idx % ROW4;
            *(uint4*)(sW + (size_t)row * WS + c * 8) = wg[(size_t)row * ROW4 + c];
        }
    }
    // cooperative A tile load: 64*K/8 uint4 (A has NNP >= m0+64 rows)
    {
        const uint4* ag = (const uint4*)(A + (size_t)m0 * K);
        constexpr int ROW4 = K / 8;
        for (int idx = tid; idx < 64 * ROW4; idx += 256) {
            int row = idx / ROW4, c = idx % ROW4;
            *(uint4*)(sA + (size_t)row * AS + c * 8) = ag[(size_t)row * ROW4 + c];
        }
    }
    __syncthreads();

    wmma::fragment<wmma::accumulator, 16, 16, 16, float> c[NFRAG];
#pragma unroll
    for (int f = 0; f < NFRAG; f++) wmma::fill_fragment(c[f], 0.f);

    for (int k = 0; k < K; k += 16) {
        wmma::fragment<wmma::matrix_a, 16, 16, 16, __half, wmma::row_major> a;
        wmma::load_matrix_sync(a, sA + (size_t)(warp_m * 16) * AS + k, AS);
#pragma unroll
        for (int f = 0; f < NFRAG; f++) {
            wmma::fragment<wmma::matrix_b, 16, 16, 16, __half, wmma::row_major> b;
            wmma::load_matrix_sync(b, sW + (size_t)k * WS + warp_n * NSPAN + f * 16, WS);
            wmma::mma_sync(c[f], a, b, c[f]);
        }
    }
    __syncthreads();   // all fragment reads done before smem reuse

#pragma unroll
    for (int f = 0; f < NFRAG; f++)
        wmma::store_matrix_sync(ep + warp_m * 16 * NC + warp_n * NSPAN + f * 16,
                                c[f], NC, wmma::mem_row_major);
    __syncthreads();

    constexpr int RPT = NC / 4;
    int j = tid % NC;
    int r0 = (tid / NC) * RPT;
    float alj = al[j], arj = ar[j];
    int head = j / D;
    for (int r = r0; r < r0 + RPT; r++) {
        int row = m0 + r;
        float v = ep[r * NC + j];
        bool valid = row < n;
        if (valid) feat[(size_t)row * NC + j] = __float2half_rn(v);
        float ev = v * alj;
        float rv = v * arj;
#pragma unroll
        for (int off = D / 2; off > 0; off >>= 1) {
            ev += __shfl_xor_sync(0xffffffffu, ev, off);
            rv += __shfl_xor_sync(0xffffffffu, rv, off);
        }
        if ((j % D) == 0 && valid) {
            el[row * H + head] = ev;
            er[row * H + head] = rv;
        }
    }
}

// smem sizes: max(W + A staging, epilogue floats)
#define SMEM1 ((INF_*(C1+8) + 64*(INF_+8)) * 2 > 64*C1*4 ? \
               (INF_*(C1+8) + 64*(INF_+8)) * 2 : 64*C1*4)
#define SMEM2 ((C1*(C2+8) + 64*(C1+8)) * 2 > 64*C2*4 ? \
               (C1*(C2+8) + 64*(C1+8)) * 2 : 64*C2*4)

// ---------------- fused per-node softmax + aggregate (single pass) ----------
template<int DT, bool ELU, bool FINAL>
__global__ void node_aggregate(const __half* __restrict__ feat,
                               const float* __restrict__ el,
                               const float* __restrict__ er,
                               const float* __restrict__ bias,
                               void* __restrict__ outp)
{
    int d = blockIdx.x * (blockDim.x >> 5) + (threadIdx.x >> 5);
    if (d >= NN) return;
    int lane = threadIdx.x & 31;
    int head = lane >> 2;
    constexpr int V = DT / 32;        // 8 or 4
    constexpr int NH2 = V / 2;        // 4 or 2

    int beg = g_rowstart[d], end = g_rowstart[d + 1];

    float sum = 0.f;
    float acc[V];
#pragma unroll
    for (int k = 0; k < V; k++) acc[k] = 0.f;

    float erv = (beg < end) ? er[d * H + head] : 0.f;

    for (int i = beg; i < end; i += 4) {
        int4 sv = *(const int4*)(g_csr + i);     // aligned: beg % 4 == 0
        int s0 = sv.x, s1 = sv.y, s2 = sv.z, s3 = sv.w;
        float l0 = el[s0 * H + head];
        float l1 = el[s1 * H + head];
        float l2 = el[s2 * H + head];
        float l3 = el[s3 * H + head];
        __half2 v0[NH2], v1[NH2], v2[NH2], v3[NH2];
        if (V == 8) {
            *(uint4*)v0 = *(const uint4*)((const __half2*)(feat + (size_t)s0 * DT) + lane * NH2);
            *(uint4*)v1 = *(const uint4*)((const __half2*)(feat + (size_t)s1 * DT) + lane * NH2);
            *(uint4*)v2 = *(const uint4*)((const __half2*)(feat + (size_t)s2 * DT) + lane * NH2);
            *(uint4*)v3 = *(const uint4*)((const __half2*)(feat + (size_t)s3 * DT) + lane * NH2);
        } else {
            *(uint2*)v0 = *(const uint2*)((const __half2*)(feat + (size_t)s0 * DT) + lane * NH2);
            *(uint2*)v1 = *(const uint2*)((const __half2*)(feat + (size_t)s1 * DT) + lane * NH2);
            *(uint2*)v2 = *(const uint2*)((const __half2*)(feat + (size_t)s2 * DT) + lane * NH2);
            *(uint2*)v3 = *(const uint2*)((const __half2*)(feat + (size_t)s3 * DT) + lane * NH2);
        }
        l0 += erv; l1 += erv; l2 += erv; l3 += erv;
        l0 = l0 > 0.f ? l0 : 0.2f * l0;
        l1 = l1 > 0.f ? l1 : 0.2f * l1;
        l2 = l2 > 0.f ? l2 : 0.2f * l2;
        l3 = l3 > 0.f ? l3 : 0.2f * l3;
        float w0 = __expf(l0), w1 = __expf(l1), w2 = __expf(l2), w3 = __expf(l3);
        sum += (w0 + w1) + (w2 + w3);
#pragma unroll
        for (int k = 0; k < NH2; k++) {
            float2 a0 = __half22float2(v0[k]);
            float2 a1 = __half22float2(v1[k]);
            float2 a2 = __half22float2(v2[k]);
            float2 a3 = __half22float2(v3[k]);
            acc[k*2+0] += w0*a0.x + w1*a1.x + w2*a2.x + w3*a3.x;
            acc[k*2+1] += w0*a0.y + w1*a1.y + w2*a2.y + w3*a3.y;
        }
    }

    float inv = (beg < end) ? 1.f / sum : 0.f;

    float vals[V];
#pragma unroll
    for (int k = 0; k < V; k++) {
        float v = acc[k] * inv + bias[lane * V + k];
        vals[k] = ELU ? (v > 0.f ? v : expm1f(v)) : v;
    }

    if (!FINAL) {
        __half2 hv[NH2];
#pragma unroll
        for (int k = 0; k < NH2; k++)
            hv[k] = __floats2half2_rn(vals[k*2+0], vals[k*2+1]);
        __half* op = (__half*)outp + (size_t)d * DT + lane * V;
        if (V == 8) *(uint4*)op = *(uint4*)hv;
        else        *(uint2*)op = *(uint2*)hv;
    } else {
#pragma unroll
        for (int off = 4; off <= 16; off <<= 1) {
#pragma unroll
            for (int k = 0; k < V; k++)
                vals[k] += __shfl_xor_sync(0xffffffffu, vals[k], off);
        }
        if (lane < 4) {
            float4 o = make_float4(vals[0] * 0.125f, vals[1] * 0.125f,
                                   vals[2] * 0.125f, vals[3] * 0.125f);
            ((float4*)((float*)outp + (size_t)d * OUTD))[lane] = o;
        }
    }
}

// ---------------- launch ----------------------------------------------------
extern "C" void kernel_launch(void* const* d_in, const int* in_sizes, int n_in,
                              void* d_out, int out_size)
{
    const float* x   = (const float*)d_in[0];
    const float* W1  = (const float*)d_in[1];
    const float* al1 = (const float*)d_in[2];
    const float* ar1 = (const float*)d_in[3];
    const float* b1  = (const float*)d_in[4];
    const float* W2  = (const float*)d_in[5];
    const float* al2 = (const float*)d_in[6];
    const float* ar2 = (const float*)d_in[7];
    const float* b2  = (const float*)d_in[8];
    const int*   src = (const int*)d_in[9];
    const int*   dst = (const int*)d_in[10];
    float* out = (float*)d_out;

    __half *x16, *W1h, *W2h, *feat1, *agg1, *feat2;
    float *el, *er;
    cudaGetSymbolAddress((void**)&x16,   g_x16);
    cudaGetSymbolAddress((void**)&W1h,   g_W1_16);
    cudaGetSymbolAddress((void**)&W2h,   g_W2_16);
    cudaGetSymbolAddress((void**)&feat1, g_feat1);
    cudaGetSymbolAddress((void**)&agg1,  g_agg1);
    cudaGetSymbolAddress((void**)&feat2, g_feat2);
    cudaGetSymbolAddress((void**)&el,    g_el);
    cudaGetSymbolAddress((void**)&er,    g_er);

    static bool attrDone = false;
    if (!attrDone) {
        cudaFuncSetAttribute((const void*)gemm_att_wmma<INF_, C1, HIDD>,
                             cudaFuncAttributeMaxDynamicSharedMemorySize, SMEM1);
        cudaFuncSetAttribute((const void*)gemm_att_wmma<C1, C2, OUTD>,
                             cudaFuncAttributeMaxDynamicSharedMemorySize, SMEM2);
        attrDone = true;
    }

    const int eBlocks    = (EE + 255) / 256;
    const int gemmBlocks = NNP / 64;
    const int nodeBlocks = (NN + 7) / 8;

    // 1: converts + cnt zero + csr dummy fill + dummy el
    k_convert<<<(NN*INF_ + 255)/256, 256>>>(x, W1, W2);
    // 2: dst histogram
    k_hist<<<eBlocks, 256>>>(dst);
    // 3: scan (pad rows to 4)
    k_scan<<<1, 1024>>>();
    // 4: layer-1 GEMM (smem-tiled)  <-- profiled slot
    gemm_att_wmma<INF_, C1, HIDD><<<gemmBlocks, 256, SMEM1>>>(x16, W1h, al1, ar1,
                                                              feat1, el, er, NN);
    // 5: scatter (needs scan only; reordered after gemm1 for profiling)
    k_scatter<<<eBlocks, 256>>>(src, dst);
    // 6: layer-1 aggregate (needs scatter + gemm1)
    node_aggregate<C1, true, false><<<nodeBlocks, 256>>>(feat1, el, er, b1, agg1);
    // 7: layer-2 GEMM
    gemm_att_wmma<C1, C2, OUTD><<<gemmBlocks, 256, SMEM2>>>(agg1, W2h, al2, ar2,
                                                            feat2, el, er, NN);
    // 8: layer-2 aggregate + head-mean
    node_aggregate<C2, false, true><<<nodeBlocks, 256>>>(feat2, el, er, b2, out);
}

// round 13
// speedup vs baseline: 1.4897x; 1.0997x over previous
#include <cuda_runtime.h>
#include <cuda_fp16.h>
#include <mma.h>
#include <math.h>

using namespace nvcuda;

#define NN   50000
#define NNP  50048           // padded to multiple of 64
#define EE   800000
#define CSRP (EE + 4*NN)     // CSR capacity with per-row pad-to-4
#define INF_ 128
#define H    8
#define HIDD 32
#define OUTD 16
#define C1   (H*HIDD)   // 256
#define C2   (H*OUTD)   // 128
#define NCP1 (C1 + 16)  // 272: W1 + wl1|wr1 columns
#define NCP2 (C2 + 16)  // 144

// ---------------- scratch (device globals, zero-initialized) ----------------
__device__ __half g_x16  [(size_t)NNP * INF_];
__device__ __half g_W1e  [INF_ * NCP1];        // W1 | wl1(8) | wr1(8)
__device__ __half g_W2e  [C1 * NCP2];          // W2 | wl2(8) | wr2(8)
__device__ __half g_feat1[(size_t)NNP * C1];   // row NN stays zero (dummy)
__device__ __half g_agg1 [(size_t)NNP * C1];
__device__ __half g_feat2[(size_t)NNP * C2];
__device__ float  g_el   [(NN + 1) * H];       // el[NN][*] = -1e30 (dummy)
__device__ float  g_er   [NN * H];
__device__ int    g_csr  [CSRP];
__device__ int    g_rowstart[NN + 1];
__device__ int    g_cnt  [NN];

// ------- merged: converts + extended-W build + zero cnt + csr/el dummies ----
__global__ void k_convert(const float* __restrict__ x,
                          const float* __restrict__ W1, const float* __restrict__ al1,
                          const float* __restrict__ ar1,
                          const float* __restrict__ W2, const float* __restrict__ al2,
                          const float* __restrict__ ar2) {
    int i = blockIdx.x * blockDim.x + threadIdx.x;
    if (i < NN * INF_) g_x16[i] = __float2half_rn(x[i]);
    if (i < INF_ * C1) {
        int k = i >> 8, j = i & 255;
        g_W1e[k * NCP1 + j] = __float2half_rn(W1[i]);
    }
    if (i < C1 * C2) {
        int k = i >> 7, j = i & 127;
        g_W2e[k * NCP2 + j] = __float2half_rn(W2[i]);
    }
    if (i < INF_ * H) {            // wl1/wr1: [128][8]
        int k = i >> 3, h = i & 7;
        float sl = 0.f, sr = 0.f;
#pragma unroll
        for (int d = 0; d < HIDD; d++) {
            float w = W1[k * C1 + h * HIDD + d];
            sl += w * al1[h * HIDD + d];
            sr += w * ar1[h * HIDD + d];
        }
        g_W1e[k * NCP1 + C1 + h]     = __float2half_rn(sl);
        g_W1e[k * NCP1 + C1 + 8 + h] = __float2half_rn(sr);
    }
    if (i < C1 * H) {              // wl2/wr2: [256][8]
        int k = i >> 3, h = i & 7;
        float sl = 0.f, sr = 0.f;
#pragma unroll
        for (int d = 0; d < OUTD; d++) {
            float w = W2[k * C2 + h * OUTD + d];
            sl += w * al2[h * OUTD + d];
            sr += w * ar2[h * OUTD + d];
        }
        g_W2e[k * NCP2 + C2 + h]     = __float2half_rn(sl);
        g_W2e[k * NCP2 + C2 + 8 + h] = __float2half_rn(sr);
    }
    if (i < NN)   g_cnt[i] = 0;
    if (i < CSRP) g_csr[i] = NN;              // dummy src (zero weight)
    if (i < H)    g_el[NN * H + i] = -1e30f;  // dummy logit -> exp = 0
}

__global__ void k_hist(const int* __restrict__ dst) {
    int e = blockIdx.x * blockDim.x + threadIdx.x;
    if (e < EE) atomicAdd(&g_cnt[dst[e]], 1);
}

// exclusive scan of counts padded to multiples of 4
__global__ void k_scan() {
    const int T = 1024;
    const int CH = (NN + T - 1) / T;
    int t = threadIdx.x;
    int base = t * CH;
    int s = 0;
#pragma unroll 4
    for (int i = 0; i < CH; i++) {
        int idx = base + i;
        if (idx < NN) s += (g_cnt[idx] + 3) & ~3;
    }
    __shared__ int sh[T];
    sh[t] = s;
    __syncthreads();
    for (int off = 1; off < T; off <<= 1) {
        int v = (t >= off) ? sh[t - off] : 0;
        __syncthreads();
        sh[t] += v;
        __syncthreads();
    }
    int run = sh[t] - s;
    for (int i = 0; i < CH; i++) {
        int idx = base + i;
        if (idx < NN) {
            int pc = (g_cnt[idx] + 3) & ~3;
            g_rowstart[idx] = run;
            g_cnt[idx] = run;      // scatter cursor
            run += pc;
        }
    }
    if (t == T - 1) g_rowstart[NN] = run;
}

__global__ void k_scatter(const int* __restrict__ src, const int* __restrict__ dst) {
    int e = blockIdx.x * blockDim.x + threadIdx.x;
    if (e >= EE) return;
    int p = atomicAdd(&g_cnt[dst[e]], 1);
    g_csr[p] = src[e];
}

// ---------------- smem-tiled tensor-core GEMM, el/er as extra columns --------
// We [K, NC+16] staged in smem; A 64-row tile staged. Warp layout 2m x 4n:
// warp computes 32 rows x NC/4 cols (B frags shared per 2 warps). warp_n==0
// also computes the 16 extra el/er columns. Epilogue: plain stores, no shfl.
template<int K, int NC, int D>
__global__ __launch_bounds__(256, 2)
void gemm_att_wmma(const __half* __restrict__ A, const __half* __restrict__ We,
                   __half* __restrict__ feat, float* __restrict__ el,
                   float* __restrict__ er, int n)
{
    constexpr int NCP = NC + 16;
    constexpr int WS = NCP + 8;           // W smem row stride (halves)
    constexpr int AS = K + 8;             // A smem row stride (halves)
    extern __shared__ char smraw[];
    __half* sW = (__half*)smraw;                       // K * WS
    __half* sA = (__half*)smraw + (size_t)K * WS;      // 64 * AS
    float*  ep = (float*)smraw;                        // epilogue reuse: 64*NCP

    constexpr int NSPAN = NC / 4;
    constexpr int NFRAG = NSPAN / 16;

    int tid = threadIdx.x;
    int wid = tid >> 5;
    int warp_m = wid & 1;                 // 2 m-warps (32 rows each)
    int warp_n = wid >> 1;                // 4 n-warps (NSPAN cols each)
    int m0 = blockIdx.x * 64;

    // cooperative W load
    {
        const uint4* wg = (const uint4*)We;
        constexpr int ROW4 = NCP / 8;
        for (int idx = tid; idx < K * ROW4; idx += 256) {
            int row = idx / ROW4, c = idx % ROW4;
            *(uint4*)(sW + (size_t)row * WS + c * 8) = wg[(size_t)row * ROW4 + c];
        }
    }
    // cooperative A tile load
    {
        const uint4* ag = (const uint4*)(A + (size_t)m0 * K);
        constexpr int ROW4 = K / 8;
        for (int idx = tid; idx < 64 * ROW4; idx += 256) {
            int row = idx / ROW4, c = idx % ROW4;
            *(uint4*)(sA + (size_t)row * AS + c * 8) = ag[(size_t)row * ROW4 + c];
        }
    }
    __syncthreads();

    wmma::fragment<wmma::accumulator, 16, 16, 16, float> c[2][NFRAG], ce[2];
#pragma unroll
    for (int mi = 0; mi < 2; mi++) {
#pragma unroll
        for (int f = 0; f < NFRAG; f++) wmma::fill_fragment(c[mi][f], 0.f);
        wmma::fill_fragment(ce[mi], 0.f);
    }

    for (int k = 0; k < K; k += 16) {
        wmma::fragment<wmma::matrix_a, 16, 16, 16, __half, wmma::row_major> a[2];
#pragma unroll
        for (int mi = 0; mi < 2; mi++)
            wmma::load_matrix_sync(a[mi], sA + (size_t)(warp_m * 32 + mi * 16) * AS + k, AS);
#pragma unroll
        for (int f = 0; f < NFRAG; f++) {
            wmma::fragment<wmma::matrix_b, 16, 16, 16, __half, wmma::row_major> b;
            wmma::load_matrix_sync(b, sW + (size_t)k * WS + warp_n * NSPAN + f * 16, WS);
#pragma unroll
            for (int mi = 0; mi < 2; mi++) wmma::mma_sync(c[mi][f], a[mi], b, c[mi][f]);
        }
        if (warp_n == 0) {    // extra el/er columns
            wmma::fragment<wmma::matrix_b, 16, 16, 16, __half, wmma::row_major> be;
            wmma::load_matrix_sync(be, sW + (size_t)k * WS + NC, WS);
#pragma unroll
            for (int mi = 0; mi < 2; mi++) wmma::mma_sync(ce[mi], a[mi], be, ce[mi]);
        }
    }
    __syncthreads();   // fragment reads done before smem reuse

#pragma unroll
    for (int mi = 0; mi < 2; mi++) {
        int rbase = (warp_m * 32 + mi * 16) * NCP;
#pragma unroll
        for (int f = 0; f < NFRAG; f++)
            wmma::store_matrix_sync(ep + rbase + warp_n * NSPAN + f * 16,
                                    c[mi][f], NCP, wmma::mem_row_major);
        if (warp_n == 0)
            wmma::store_matrix_sync(ep + rbase + NC, ce[mi], NCP, wmma::mem_row_major);
    }
    __syncthreads();

    // feat: thread owns column j for RPT rows (plain converts+stores)
    {
        constexpr int RPT = NC / 4;          // 64 or 32
        int j = tid % NC;
        int r0 = (tid / NC) * RPT;
        for (int r = r0; r < r0 + RPT; r++) {
            int row = m0 + r;
            if (row < n) feat[(size_t)row * NC + j] = __float2half_rn(ep[r * NCP + j]);
        }
    }
    // el/er: 64 rows x 16 cols = 1024 entries, 4 per thread
    {
        int e0 = tid * 4;
#pragma unroll
        for (int e = e0; e < e0 + 4; e++) {
            int r = e >> 4, cc = e & 15;
            int row = m0 + r;
            if (row < n) {
                float v = ep[r * NCP + NC + cc];
                if (cc < 8) el[row * H + cc] = v;
                else        er[row * H + (cc - 8)] = v;
            }
        }
    }
}

// smem: max(W + A staging, epilogue floats)
#define SMEM_G(K, NC) (((K)*((NC)+16+8) + 64*((K)+8)) * 2 > 64*((NC)+16)*4 ? \
                       ((K)*((NC)+16+8) + 64*((K)+8)) * 2 : 64*((NC)+16)*4)
#define SMEM1 SMEM_G(INF_, C1)
#define SMEM2 SMEM_G(C1, C2)

// ---------------- fused per-node softmax + aggregate (single pass) ----------
template<int DT, bool ELU, bool FINAL>
__global__ void node_aggregate(const __half* __restrict__ feat,
                               const float* __restrict__ el,
                               const float* __restrict__ er,
                               const float* __restrict__ bias,
                               void* __restrict__ outp)
{
    int d = blockIdx.x * (blockDim.x >> 5) + (threadIdx.x >> 5);
    if (d >= NN) return;
    int lane = threadIdx.x & 31;
    int head = lane >> 2;
    constexpr int V = DT / 32;        // 8 or 4
    constexpr int NH2 = V / 2;        // 4 or 2

    int beg = g_rowstart[d], end = g_rowstart[d + 1];

    float sum = 0.f;
    float acc[V];
#pragma unroll
    for (int k = 0; k < V; k++) acc[k] = 0.f;

    float erv = (beg < end) ? er[d * H + head] : 0.f;

    for (int i = beg; i < end; i += 4) {
        int4 sv = *(const int4*)(g_csr + i);     // aligned: beg % 4 == 0
        int s0 = sv.x, s1 = sv.y, s2 = sv.z, s3 = sv.w;
        float l0 = el[s0 * H + head];
        float l1 = el[s1 * H + head];
        float l2 = el[s2 * H + head];
        float l3 = el[s3 * H + head];
        __half2 v0[NH2], v1[NH2], v2[NH2], v3[NH2];
        if (V == 8) {
            *(uint4*)v0 = *(const uint4*)((const __half2*)(feat + (size_t)s0 * DT) + lane * NH2);
            *(uint4*)v1 = *(const uint4*)((const __half2*)(feat + (size_t)s1 * DT) + lane * NH2);
            *(uint4*)v2 = *(const uint4*)((const __half2*)(feat + (size_t)s2 * DT) + lane * NH2);
            *(uint4*)v3 = *(const uint4*)((const __half2*)(feat + (size_t)s3 * DT) + lane * NH2);
        } else {
            *(uint2*)v0 = *(const uint2*)((const __half2*)(feat + (size_t)s0 * DT) + lane * NH2);
            *(uint2*)v1 = *(const uint2*)((const __half2*)(feat + (size_t)s1 * DT) + lane * NH2);
            *(uint2*)v2 = *(const uint2*)((const __half2*)(feat + (size_t)s2 * DT) + lane * NH2);
            *(uint2*)v3 = *(const uint2*)((const __half2*)(feat + (size_t)s3 * DT) + lane * NH2);
        }
        l0 += erv; l1 += erv; l2 += erv; l3 += erv;
        l0 = l0 > 0.f ? l0 : 0.2f * l0;
        l1 = l1 > 0.f ? l1 : 0.2f * l1;
        l2 = l2 > 0.f ? l2 : 0.2f * l2;
        l3 = l3 > 0.f ? l3 : 0.2f * l3;
        float w0 = __expf(l0), w1 = __expf(l1), w2 = __expf(l2), w3 = __expf(l3);
        sum += (w0 + w1) + (w2 + w3);
#pragma unroll
        for (int k = 0; k < NH2; k++) {
            float2 a0 = __half22float2(v0[k]);
            float2 a1 = __half22float2(v1[k]);
            float2 a2 = __half22float2(v2[k]);
            float2 a3 = __half22float2(v3[k]);
            acc[k*2+0] += w0*a0.x + w1*a1.x + w2*a2.x + w3*a3.x;
            acc[k*2+1] += w0*a0.y + w1*a1.y + w2*a2.y + w3*a3.y;
        }
    }

    float inv = (beg < end) ? 1.f / sum : 0.f;

    float vals[V];
#pragma unroll
    for (int k = 0; k < V; k++) {
        float v = acc[k] * inv + bias[lane * V + k];
        vals[k] = ELU ? (v > 0.f ? v : expm1f(v)) : v;
    }

    if (!FINAL) {
        __half2 hv[NH2];
#pragma unroll
        for (int k = 0; k < NH2; k++)
            hv[k] = __floats2half2_rn(vals[k*2+0], vals[k*2+1]);
        __half* op = (__half*)outp + (size_t)d * DT + lane * V;
        if (V == 8) *(uint4*)op = *(uint4*)hv;
        else        *(uint2*)op = *(uint2*)hv;
    } else {
#pragma unroll
        for (int off = 4; off <= 16; off <<= 1) {
#pragma unroll
            for (int k = 0; k < V; k++)
                vals[k] += __shfl_xor_sync(0xffffffffu, vals[k], off);
        }
        if (lane < 4) {
            float4 o = make_float4(vals[0] * 0.125f, vals[1] * 0.125f,
                                   vals[2] * 0.125f, vals[3] * 0.125f);
            ((float4*)((float*)outp + (size_t)d * OUTD))[lane] = o;
        }
    }
}

// ---------------- launch ----------------------------------------------------
extern "C" void kernel_launch(void* const* d_in, const int* in_sizes, int n_in,
                              void* d_out, int out_size)
{
    const float* x   = (const float*)d_in[0];
    const float* W1  = (const float*)d_in[1];
    const float* al1 = (const float*)d_in[2];
    const float* ar1 = (const float*)d_in[3];
    const float* b1  = (const float*)d_in[4];
    const float* W2  = (const float*)d_in[5];
    const float* al2 = (const float*)d_in[6];
    const float* ar2 = (const float*)d_in[7];
    const float* b2  = (const float*)d_in[8];
    const int*   src = (const int*)d_in[9];
    const int*   dst = (const int*)d_in[10];
    float* out = (float*)d_out;

    __half *x16, *W1e, *W2e, *feat1, *agg1, *feat2;
    float *el, *er;
    cudaGetSymbolAddress((void**)&x16,   g_x16);
    cudaGetSymbolAddress((void**)&W1e,   g_W1e);
    cudaGetSymbolAddress((void**)&W2e,   g_W2e);
    cudaGetSymbolAddress((void**)&feat1, g_feat1);
    cudaGetSymbolAddress((void**)&agg1,  g_agg1);
    cudaGetSymbolAddress((void**)&feat2, g_feat2);
    cudaGetSymbolAddress((void**)&el,    g_el);
    cudaGetSymbolAddress((void**)&er,    g_er);

    static bool attrDone = false;
    if (!attrDone) {
        cudaFuncSetAttribute((const void*)gemm_att_wmma<INF_, C1, HIDD>,
                             cudaFuncAttributeMaxDynamicSharedMemorySize, SMEM1);
        cudaFuncSetAttribute((const void*)gemm_att_wmma<C1, C2, OUTD>,
                             cudaFuncAttributeMaxDynamicSharedMemorySize, SMEM2);
        attrDone = true;
    }

    const int eBlocks    = (EE + 255) / 256;
    const int gemmBlocks = NNP / 64;
    const int nodeBlocks = (NN + 7) / 8;

    // 1: converts + extended W + cnt zero + csr/el dummies
    k_convert<<<(NN*INF_ + 255)/256, 256>>>(x, W1, al1, ar1, W2, al2, ar2);
    // 2: dst histogram
    k_hist<<<eBlocks, 256>>>(dst);
    // 3: scan (pad rows to 4)
    k_scan<<<1, 1024>>>();
    // 4: layer-1 GEMM  <-- profiled slot
    gemm_att_wmma<INF_, C1, HIDD><<<gemmBlocks, 256, SMEM1>>>(x16, W1e, feat1, el, er, NN);
    // 5: scatter
    k_scatter<<<eBlocks, 256>>>(src, dst);
    // 6: layer-1 aggregate
    node_aggregate<C1, true, false><<<nodeBlocks, 256>>>(feat1, el, er, b1, agg1);
    // 7: layer-2 GEMM
    gemm_att_wmma<C1, C2, OUTD><<<gemmBlocks, 256, SMEM2>>>(agg1, W2e, feat2, el, er, NN);
    // 8: layer-2 aggregate + head-mean
    node_aggregate<C2, false, true><<<nodeBlocks, 256>>>(feat2, el, er, b2, out);
}

// round 14
// speedup vs baseline: 1.6957x; 1.1383x over previous
#include <cuda_runtime.h>
#include <cuda_fp16.h>
#include <mma.h>
#include <math.h>

using namespace nvcuda;

#define NN   50000
#define NNP  50048           // padded to multiple of 64
#define EE   800000
#define CSRP (EE + 4*NN)     // CSR capacity with per-row pad-to-4
#define INF_ 128
#define H    8
#define HIDD 32
#define OUTD 16
#define C1   (H*HIDD)   // 256
#define C2   (H*OUTD)   // 128
#define NCP1 (C1 + 16)  // 272: W1 + wl1|wr1 columns
#define NCP2 (C2 + 16)  // 144

// ---------------- scratch (device globals, zero-initialized) ----------------
__device__ __half g_x16  [(size_t)NNP * INF_];
__device__ __half g_W1e  [INF_ * NCP1];        // W1 | wl1(8) | wr1(8)
__device__ __half g_W2e  [C1 * NCP2];          // W2 | wl2(8) | wr2(8)
__device__ __half g_feat1[(size_t)NNP * C1];   // row NN stays zero (dummy)
__device__ __half g_agg1 [(size_t)NNP * C1];
__device__ __half g_feat2[(size_t)NNP * C2];
__device__ float  g_el   [(NN + 1) * H];       // el[NN][*] = -1e30 (dummy)
__device__ float  g_er   [NN * H];
__device__ int    g_csr  [CSRP];
__device__ int    g_rowstart[NN + 1];
__device__ int    g_cnt  [NN];

// ------- merged: converts + extended-W build + zero cnt + csr/el dummies ----
__global__ void k_convert(const float* __restrict__ x,
                          const float* __restrict__ W1, const float* __restrict__ al1,
                          const float* __restrict__ ar1,
                          const float* __restrict__ W2, const float* __restrict__ al2,
                          const float* __restrict__ ar2) {
    int i = blockIdx.x * blockDim.x + threadIdx.x;
    if (i < NN * INF_) g_x16[i] = __float2half_rn(x[i]);
    if (i < INF_ * C1) {
        int k = i >> 8, j = i & 255;
        g_W1e[k * NCP1 + j] = __float2half_rn(W1[i]);
    }
    if (i < C1 * C2) {
        int k = i >> 7, j = i & 127;
        g_W2e[k * NCP2 + j] = __float2half_rn(W2[i]);
    }
    if (i < INF_ * H) {            // wl1/wr1: [128][8]
        int k = i >> 3, h = i & 7;
        float sl = 0.f, sr = 0.f;
#pragma unroll
        for (int d = 0; d < HIDD; d++) {
            float w = W1[k * C1 + h * HIDD + d];
            sl += w * al1[h * HIDD + d];
            sr += w * ar1[h * HIDD + d];
        }
        g_W1e[k * NCP1 + C1 + h]     = __float2half_rn(sl);
        g_W1e[k * NCP1 + C1 + 8 + h] = __float2half_rn(sr);
    }
    if (i < C1 * H) {              // wl2/wr2: [256][8]
        int k = i >> 3, h = i & 7;
        float sl = 0.f, sr = 0.f;
#pragma unroll
        for (int d = 0; d < OUTD; d++) {
            float w = W2[k * C2 + h * OUTD + d];
            sl += w * al2[h * OUTD + d];
            sr += w * ar2[h * OUTD + d];
        }
        g_W2e[k * NCP2 + C2 + h]     = __float2half_rn(sl);
        g_W2e[k * NCP2 + C2 + 8 + h] = __float2half_rn(sr);
    }
    if (i < NN)   g_cnt[i] = 0;
    if (i < CSRP) g_csr[i] = NN;              // dummy src (zero weight)
    if (i < H)    g_el[NN * H + i] = -1e30f;  // dummy logit -> exp = 0
}

__global__ void k_hist(const int* __restrict__ dst) {
    int e = blockIdx.x * blockDim.x + threadIdx.x;
    if (e < EE) atomicAdd(&g_cnt[dst[e]], 1);
}

// ---- coalesced tile-based exclusive scan (counts padded to multiples of 4) --
// One block, 1024 threads, 49 tiles of 1024. Per tile: coalesced load,
// warp shfl-scan, cross-warp smem combine (3 bars), coalesced stores.
__global__ void k_scan() {
    __shared__ int warpsum[32];
    int t = threadIdx.x;
    int lane = t & 31, w = t >> 5;
    int offset = 0;

    for (int base = 0; base < NN; base += 1024) {
        int idx = base + t;
        int c  = (idx < NN) ? g_cnt[idx] : 0;
        int pc = (c + 3) & ~3;

        // warp inclusive scan
        int v = pc;
#pragma unroll
        for (int o = 1; o < 32; o <<= 1) {
            int u = __shfl_up_sync(0xffffffffu, v, o);
            if (lane >= o) v += u;
        }
        if (lane == 31) warpsum[w] = v;
        __syncthreads();
        if (w == 0) {
            int s = warpsum[lane];
#pragma unroll
            for (int o = 1; o < 32; o <<= 1) {
                int u = __shfl_up_sync(0xffffffffu, s, o);
                if (lane >= o) s += u;
            }
            warpsum[lane] = s;
        }
        __syncthreads();
        int incl = v + (w > 0 ? warpsum[w - 1] : 0) + offset;
        int excl = incl - pc;
        if (idx < NN) {
            g_rowstart[idx] = excl;
            g_cnt[idx] = excl;       // scatter cursor
        }
        int total = warpsum[31];
        offset += total;
        __syncthreads();             // protect warpsum before next tile
    }
    if (t == 0) g_rowstart[NN] = offset;
}

__global__ void k_scatter(const int* __restrict__ src, const int* __restrict__ dst) {
    int e = blockIdx.x * blockDim.x + threadIdx.x;
    if (e >= EE) return;
    int p = atomicAdd(&g_cnt[dst[e]], 1);
    g_csr[p] = src[e];
}

// ---------------- smem-tiled tensor-core GEMM, el/er as extra columns --------
template<int K, int NC, int D>
__global__ __launch_bounds__(256, 2)
void gemm_att_wmma(const __half* __restrict__ A, const __half* __restrict__ We,
                   __half* __restrict__ feat, float* __restrict__ el,
                   float* __restrict__ er, int n)
{
    constexpr int NCP = NC + 16;
    constexpr int WS = NCP + 8;           // W smem row stride (halves)
    constexpr int AS = K + 8;             // A smem row stride (halves)
    extern __shared__ char smraw[];
    __half* sW = (__half*)smraw;                       // K * WS
    __half* sA = (__half*)smraw + (size_t)K * WS;      // 64 * AS
    float*  ep = (float*)smraw;                        // epilogue reuse: 64*NCP

    constexpr int NSPAN = NC / 4;
    constexpr int NFRAG = NSPAN / 16;

    int tid = threadIdx.x;
    int wid = tid >> 5;
    int warp_m = wid & 1;                 // 2 m-warps (32 rows each)
    int warp_n = wid >> 1;                // 4 n-warps (NSPAN cols each)
    int m0 = blockIdx.x * 64;

    // cooperative W load
    {
        const uint4* wg = (const uint4*)We;
        constexpr int ROW4 = NCP / 8;
        for (int idx = tid; idx < K * ROW4; idx += 256) {
            int row = idx / ROW4, c = idx % ROW4;
            *(uint4*)(sW + (size_t)row * WS + c * 8) = wg[(size_t)row * ROW4 + c];
        }
    }
    // cooperative A tile load
    {
        const uint4* ag = (const uint4*)(A + (size_t)m0 * K);
        constexpr int ROW4 = K / 8;
        for (int idx = tid; idx < 64 * ROW4; idx += 256) {
            int row = idx / ROW4, c = idx % ROW4;
            *(uint4*)(sA + (size_t)row * AS + c * 8) = ag[(size_t)row * ROW4 + c];
        }
    }
    __syncthreads();

    wmma::fragment<wmma::accumulator, 16, 16, 16, float> c[2][NFRAG], ce[2];
#pragma unroll
    for (int mi = 0; mi < 2; mi++) {
#pragma unroll
        for (int f = 0; f < NFRAG; f++) wmma::fill_fragment(c[mi][f], 0.f);
        wmma::fill_fragment(ce[mi], 0.f);
    }

    for (int k = 0; k < K; k += 16) {
        wmma::fragment<wmma::matrix_a, 16, 16, 16, __half, wmma::row_major> a[2];
#pragma unroll
        for (int mi = 0; mi < 2; mi++)
            wmma::load_matrix_sync(a[mi], sA + (size_t)(warp_m * 32 + mi * 16) * AS + k, AS);
#pragma unroll
        for (int f = 0; f < NFRAG; f++) {
            wmma::fragment<wmma::matrix_b, 16, 16, 16, __half, wmma::row_major> b;
            wmma::load_matrix_sync(b, sW + (size_t)k * WS + warp_n * NSPAN + f * 16, WS);
#pragma unroll
            for (int mi = 0; mi < 2; mi++) wmma::mma_sync(c[mi][f], a[mi], b, c[mi][f]);
        }
        if (warp_n == 0) {    // extra el/er columns
            wmma::fragment<wmma::matrix_b, 16, 16, 16, __half, wmma::row_major> be;
            wmma::load_matrix_sync(be, sW + (size_t)k * WS + NC, WS);
#pragma unroll
            for (int mi = 0; mi < 2; mi++) wmma::mma_sync(ce[mi], a[mi], be, ce[mi]);
        }
    }
    __syncthreads();   // fragment reads done before smem reuse

#pragma unroll
    for (int mi = 0; mi < 2; mi++) {
        int rbase = (warp_m * 32 + mi * 16) * NCP;
#pragma unroll
        for (int f = 0; f < NFRAG; f++)
            wmma::store_matrix_sync(ep + rbase + warp_n * NSPAN + f * 16,
                                    c[mi][f], NCP, wmma::mem_row_major);
        if (warp_n == 0)
            wmma::store_matrix_sync(ep + rbase + NC, ce[mi], NCP, wmma::mem_row_major);
    }
    __syncthreads();

    // feat: thread owns column j for RPT rows
    {
        constexpr int RPT = NC / 4;          // 64 or 32
        int j = tid % NC;
        int r0 = (tid / NC) * RPT;
        for (int r = r0; r < r0 + RPT; r++) {
            int row = m0 + r;
            if (row < n) feat[(size_t)row * NC + j] = __float2half_rn(ep[r * NCP + j]);
        }
    }
    // el/er: 64 rows x 16 cols = 1024 entries, 4 per thread
    {
        int e0 = tid * 4;
#pragma unroll
        for (int e = e0; e < e0 + 4; e++) {
            int r = e >> 4, cc = e & 15;
            int row = m0 + r;
            if (row < n) {
                float v = ep[r * NCP + NC + cc];
                if (cc < 8) el[row * H + cc] = v;
                else        er[row * H + (cc - 8)] = v;
            }
        }
    }
}

// smem: max(W + A staging, epilogue floats)
#define SMEM_G(K, NC) (((K)*((NC)+16+8) + 64*((K)+8)) * 2 > 64*((NC)+16)*4 ? \
                       ((K)*((NC)+16+8) + 64*((K)+8)) * 2 : 64*((NC)+16)*4)
#define SMEM1 SMEM_G(INF_, C1)
#define SMEM2 SMEM_G(C1, C2)

// ---------------- fused per-node softmax + aggregate (single pass) ----------
template<int DT, bool ELU, bool FINAL>
__global__ void node_aggregate(const __half* __restrict__ feat,
                               const float* __restrict__ el,
                               const float* __restrict__ er,
                               const float* __restrict__ bias,
                               void* __restrict__ outp)
{
    int d = blockIdx.x * (blockDim.x >> 5) + (threadIdx.x >> 5);
    if (d >= NN) return;
    int lane = threadIdx.x & 31;
    int head = lane >> 2;
    constexpr int V = DT / 32;        // 8 or 4
    constexpr int NH2 = V / 2;        // 4 or 2

    int beg = g_rowstart[d], end = g_rowstart[d + 1];

    float sum = 0.f;
    float acc[V];
#pragma unroll
    for (int k = 0; k < V; k++) acc[k] = 0.f;

    float erv = (beg < end) ? er[d * H + head] : 0.f;

    for (int i = beg; i < end; i += 4) {
        int4 sv = *(const int4*)(g_csr + i);     // aligned: beg % 4 == 0
        int s0 = sv.x, s1 = sv.y, s2 = sv.z, s3 = sv.w;
        float l0 = el[s0 * H + head];
        float l1 = el[s1 * H + head];
        float l2 = el[s2 * H + head];
        float l3 = el[s3 * H + head];
        __half2 v0[NH2], v1[NH2], v2[NH2], v3[NH2];
        if (V == 8) {
            *(uint4*)v0 = *(const uint4*)((const __half2*)(feat + (size_t)s0 * DT) + lane * NH2);
            *(uint4*)v1 = *(const uint4*)((const __half2*)(feat + (size_t)s1 * DT) + lane * NH2);
            *(uint4*)v2 = *(const uint4*)((const __half2*)(feat + (size_t)s2 * DT) + lane * NH2);
            *(uint4*)v3 = *(const uint4*)((const __half2*)(feat + (size_t)s3 * DT) + lane * NH2);
        } else {
            *(uint2*)v0 = *(const uint2*)((const __half2*)(feat + (size_t)s0 * DT) + lane * NH2);
            *(uint2*)v1 = *(const uint2*)((const __half2*)(feat + (size_t)s1 * DT) + lane * NH2);
            *(uint2*)v2 = *(const uint2*)((const __half2*)(feat + (size_t)s2 * DT) + lane * NH2);
            *(uint2*)v3 = *(const uint2*)((const __half2*)(feat + (size_t)s3 * DT) + lane * NH2);
        }
        l0 += erv; l1 += erv; l2 += erv; l3 += erv;
        l0 = l0 > 0.f ? l0 : 0.2f * l0;
        l1 = l1 > 0.f ? l1 : 0.2f * l1;
        l2 = l2 > 0.f ? l2 : 0.2f * l2;
        l3 = l3 > 0.f ? l3 : 0.2f * l3;
        float w0 = __expf(l0), w1 = __expf(l1), w2 = __expf(l2), w3 = __expf(l3);
        sum += (w0 + w1) + (w2 + w3);
#pragma unroll
        for (int k = 0; k < NH2; k++) {
            float2 a0 = __half22float2(v0[k]);
            float2 a1 = __half22float2(v1[k]);
            float2 a2 = __half22float2(v2[k]);
            float2 a3 = __half22float2(v3[k]);
            acc[k*2+0] += w0*a0.x + w1*a1.x + w2*a2.x + w3*a3.x;
            acc[k*2+1] += w0*a0.y + w1*a1.y + w2*a2.y + w3*a3.y;
        }
    }

    float inv = (beg < end) ? 1.f / sum : 0.f;

    float vals[V];
#pragma unroll
    for (int k = 0; k < V; k++) {
        float v = acc[k] * inv + bias[lane * V + k];
        vals[k] = ELU ? (v > 0.f ? v : expm1f(v)) : v;
    }

    if (!FINAL) {
        __half2 hv[NH2];
#pragma unroll
        for (int k = 0; k < NH2; k++)
            hv[k] = __floats2half2_rn(vals[k*2+0], vals[k*2+1]);
        __half* op = (__half*)outp + (size_t)d * DT + lane * V;
        if (V == 8) *(uint4*)op = *(uint4*)hv;
        else        *(uint2*)op = *(uint2*)hv;
    } else {
#pragma unroll
        for (int off = 4; off <= 16; off <<= 1) {
#pragma unroll
            for (int k = 0; k < V; k++)
                vals[k] += __shfl_xor_sync(0xffffffffu, vals[k], off);
        }
        if (lane < 4) {
            float4 o = make_float4(vals[0] * 0.125f, vals[1] * 0.125f,
                                   vals[2] * 0.125f, vals[3] * 0.125f);
            ((float4*)((float*)outp + (size_t)d * OUTD))[lane] = o;
        }
    }
}

// ---------------- launch ----------------------------------------------------
extern "C" void kernel_launch(void* const* d_in, const int* in_sizes, int n_in,
                              void* d_out, int out_size)
{
    const float* x   = (const float*)d_in[0];
    const float* W1  = (const float*)d_in[1];
    const float* al1 = (const float*)d_in[2];
    const float* ar1 = (const float*)d_in[3];
    const float* b1  = (const float*)d_in[4];
    const float* W2  = (const float*)d_in[5];
    const float* al2 = (const float*)d_in[6];
    const float* ar2 = (const float*)d_in[7];
    const float* b2  = (const float*)d_in[8];
    const int*   src = (const int*)d_in[9];
    const int*   dst = (const int*)d_in[10];
    float* out = (float*)d_out;

    __half *x16, *W1e, *W2e, *feat1, *agg1, *feat2;
    float *el, *er;
    cudaGetSymbolAddress((void**)&x16,   g_x16);
    cudaGetSymbolAddress((void**)&W1e,   g_W1e);
    cudaGetSymbolAddress((void**)&W2e,   g_W2e);
    cudaGetSymbolAddress((void**)&feat1, g_feat1);
    cudaGetSymbolAddress((void**)&agg1,  g_agg1);
    cudaGetSymbolAddress((void**)&feat2, g_feat2);
    cudaGetSymbolAddress((void**)&el,    g_el);
    cudaGetSymbolAddress((void**)&er,    g_er);

    static bool attrDone = false;
    if (!attrDone) {
        cudaFuncSetAttribute((const void*)gemm_att_wmma<INF_, C1, HIDD>,
                             cudaFuncAttributeMaxDynamicSharedMemorySize, SMEM1);
        cudaFuncSetAttribute((const void*)gemm_att_wmma<C1, C2, OUTD>,
                             cudaFuncAttributeMaxDynamicSharedMemorySize, SMEM2);
        attrDone = true;
    }

    const int eBlocks    = (EE + 255) / 256;
    const int gemmBlocks = NNP / 64;
    const int nodeBlocks = (NN + 7) / 8;

    // 1: converts + extended W + cnt zero + csr/el dummies
    k_convert<<<(NN*INF_ + 255)/256, 256>>>(x, W1, al1, ar1, W2, al2, ar2);
    // 2: dst histogram
    k_hist<<<eBlocks, 256>>>(dst);
    // 3: layer-1 GEMM (needs convert only)
    gemm_att_wmma<INF_, C1, HIDD><<<gemmBlocks, 256, SMEM1>>>(x16, W1e, feat1, el, er, NN);
    // 4: coalesced scan (needs hist)  <-- profiled slot
    k_scan<<<1, 1024>>>();
    // 5: scatter
    k_scatter<<<eBlocks, 256>>>(src, dst);
    // 6: layer-1 aggregate
    node_aggregate<C1, true, false><<<nodeBlocks, 256>>>(feat1, el, er, b1, agg1);
    // 7: layer-2 GEMM
    gemm_att_wmma<C1, C2, OUTD><<<gemmBlocks, 256, SMEM2>>>(agg1, W2e, feat2, el, er, NN);
    // 8: layer-2 aggregate + head-mean
    node_aggregate<C2, false, true><<<nodeBlocks, 256>>>(feat2, el, er, b2, out);
}

// round 15
// speedup vs baseline: 1.8819x; 1.1098x over previous
#include <cuda_runtime.h>
#include <cuda_fp16.h>
#include <mma.h>
#include <math.h>

using namespace nvcuda;

#define NN   50000
#define NNP  50048           // padded to multiple of 64
#define EE   800000
#define CSRP (EE + 4*NN)     // CSR capacity with per-row pad-to-4
#define INF_ 128
#define H    8
#define HIDD 32
#define OUTD 16
#define C1   (H*HIDD)   // 256
#define C2   (H*OUTD)   // 128
#define NCP1 (C1 + 16)  // 272
#define NCP2 (C2 + 16)  // 144

#define SCAN_T  1024
#define SCAN_CH 49                    // 1024*49 = 50176 >= NN
#define SCAN_NP (SCAN_T * SCAN_CH)
#define SCAN_SMEM ((SCAN_NP + SCAN_T) * 4)

// ---------------- scratch (device globals, zero-initialized) ----------------
__device__ __half g_x16  [(size_t)NNP * INF_];
__device__ __half g_W1e  [INF_ * NCP1];        // W1 | wl1(8) | wr1(8)
__device__ __half g_W2e  [C1 * NCP2];          // W2 | wl2(8) | wr2(8)
__device__ __half g_feat1[(size_t)NNP * C1];   // row NN stays zero (dummy)
__device__ __half g_agg1 [(size_t)NNP * C1];
__device__ __half g_feat2[(size_t)NNP * C2];
__device__ float  g_el   [(NN + 1) * H];       // el[NN][*] = -1e30 (dummy)
__device__ float  g_er   [NN * H];
__device__ int    g_csr  [CSRP];
__device__ int    g_rowstart[NN + 1];
__device__ int    g_cnt  [NN];

// ------- merged: converts + extended-W build + zero cnt + csr/el dummies ----
__global__ void k_convert(const float* __restrict__ x,
                          const float* __restrict__ W1, const float* __restrict__ al1,
                          const float* __restrict__ ar1,
                          const float* __restrict__ W2, const float* __restrict__ al2,
                          const float* __restrict__ ar2) {
    int i = blockIdx.x * blockDim.x + threadIdx.x;
    if (i < NN * INF_) g_x16[i] = __float2half_rn(x[i]);
    if (i < INF_ * C1) {
        int k = i >> 8, j = i & 255;
        g_W1e[k * NCP1 + j] = __float2half_rn(W1[i]);
    }
    if (i < C1 * C2) {
        int k = i >> 7, j = i & 127;
        g_W2e[k * NCP2 + j] = __float2half_rn(W2[i]);
    }
    if (i < INF_ * H) {            // wl1/wr1: [128][8]
        int k = i >> 3, h = i & 7;
        float sl = 0.f, sr = 0.f;
#pragma unroll
        for (int d = 0; d < HIDD; d++) {
            float w = W1[k * C1 + h * HIDD + d];
            sl += w * al1[h * HIDD + d];
            sr += w * ar1[h * HIDD + d];
        }
        g_W1e[k * NCP1 + C1 + h]     = __float2half_rn(sl);
        g_W1e[k * NCP1 + C1 + 8 + h] = __float2half_rn(sr);
    }
    if (i < C1 * H) {              // wl2/wr2: [256][8]
        int k = i >> 3, h = i & 7;
        float sl = 0.f, sr = 0.f;
#pragma unroll
        for (int d = 0; d < OUTD; d++) {
            float w = W2[k * C2 + h * OUTD + d];
            sl += w * al2[h * OUTD + d];
            sr += w * ar2[h * OUTD + d];
        }
        g_W2e[k * NCP2 + C2 + h]     = __float2half_rn(sl);
        g_W2e[k * NCP2 + C2 + 8 + h] = __float2half_rn(sr);
    }
    if (i < NN)   g_cnt[i] = 0;
    if (i < CSRP) g_csr[i] = NN;              // dummy src (zero weight)
    if (i < H)    g_el[NN * H + i] = -1e30f;  // dummy logit -> exp = 0
}

__global__ void k_hist(const int* __restrict__ dst) {
    int e = blockIdx.x * blockDim.x + threadIdx.x;
    if (e < EE) atomicAdd(&g_cnt[dst[e]], 1);
}

// ---- single-block scan, O(1) barriers: smem-buffered, coalesced both ways ---
__global__ void k_scan() {
    extern __shared__ int S[];            // [SCAN_NP] values + [SCAN_T] totals
    __shared__ int wsum[32];
    int* T = S + SCAN_NP;
    int t = threadIdx.x;
    int lane = t & 31, w = t >> 5;

    // 1. coalesced global load (all 49 in flight), pad, store to smem
#pragma unroll
    for (int j = 0; j < SCAN_CH; j++) {
        int idx = j * SCAN_T + t;
        int c = (idx < NN) ? g_cnt[idx] : 0;
        S[idx] = (c + 3) & ~3;
    }
    __syncthreads();

    // 2. per-thread chunk scan (stride-49 lanes: gcd(49,32)=1, conflict-free)
    int base = t * SCAN_CH;
    int run = 0;
#pragma unroll
    for (int i = 0; i < SCAN_CH; i++) {
        int v = S[base + i];
        S[base + i] = run;               // exclusive within chunk
        run += v;
    }
    T[t] = run;
    __syncthreads();

    // 3. block exclusive scan of chunk totals
    int v = T[t], inc = v;
#pragma unroll
    for (int o = 1; o < 32; o <<= 1) {
        int u = __shfl_up_sync(0xffffffffu, inc, o);
        if (lane >= o) inc += u;
    }
    if (lane == 31) wsum[w] = inc;
    __syncthreads();
    if (w == 0) {
        int s = wsum[lane];
#pragma unroll
        for (int o = 1; o < 32; o <<= 1) {
            int u = __shfl_up_sync(0xffffffffu, s, o);
            if (lane >= o) s += u;
        }
        wsum[lane] = s;
    }
    __syncthreads();
    int chunk_off = inc - v + (w > 0 ? wsum[w - 1] : 0);
    T[t] = chunk_off;
    __syncthreads();

    // 4. coalesced writeback
#pragma unroll
    for (int j = 0; j < SCAN_CH; j++) {
        int idx = j * SCAN_T + t;
        if (idx < NN) {
            int excl = S[idx] + T[idx / SCAN_CH];
            g_rowstart[idx] = excl;
            g_cnt[idx] = excl;           // scatter cursor
        }
    }
    if (t == SCAN_T - 1) g_rowstart[NN] = chunk_off + run;
}

__global__ void k_scatter(const int* __restrict__ src, const int* __restrict__ dst) {
    int e = blockIdx.x * blockDim.x + threadIdx.x;
    if (e >= EE) return;
    int p = atomicAdd(&g_cnt[dst[e]], 1);
    g_csr[p] = src[e];
}

// ---------------- smem-tiled tensor-core GEMM, el/er as extra columns --------
template<int K, int NC, int D>
__global__ __launch_bounds__(256, 2)
void gemm_att_wmma(const __half* __restrict__ A, const __half* __restrict__ We,
                   __half* __restrict__ feat, float* __restrict__ el,
                   float* __restrict__ er, int n)
{
    constexpr int NCP = NC + 16;
    constexpr int WS = NCP + 8;
    constexpr int AS = K + 8;
    extern __shared__ char smraw[];
    __half* sW = (__half*)smraw;
    __half* sA = (__half*)smraw + (size_t)K * WS;
    float*  ep = (float*)smraw;

    constexpr int NSPAN = NC / 4;
    constexpr int NFRAG = NSPAN / 16;

    int tid = threadIdx.x;
    int wid = tid >> 5;
    int warp_m = wid & 1;
    int warp_n = wid >> 1;
    int m0 = blockIdx.x * 64;

    {
        const uint4* wg = (const uint4*)We;
        constexpr int ROW4 = NCP / 8;
        for (int idx = tid; idx < K * ROW4; idx += 256) {
            int row = idx / ROW4, c = idx % ROW4;
            *(uint4*)(sW + (size_t)row * WS + c * 8) = wg[(size_t)row * ROW4 + c];
        }
    }
    {
        const uint4* ag = (const uint4*)(A + (size_t)m0 * K);
        constexpr int ROW4 = K / 8;
        for (int idx = tid; idx < 64 * ROW4; idx += 256) {
            int row = idx / ROW4, c = idx % ROW4;
            *(uint4*)(sA + (size_t)row * AS + c * 8) = ag[(size_t)row * ROW4 + c];
        }
    }
    __syncthreads();

    wmma::fragment<wmma::accumulator, 16, 16, 16, float> c[2][NFRAG], ce[2];
#pragma unroll
    for (int mi = 0; mi < 2; mi++) {
#pragma unroll
        for (int f = 0; f < NFRAG; f++) wmma::fill_fragment(c[mi][f], 0.f);
        wmma::fill_fragment(ce[mi], 0.f);
    }

    for (int k = 0; k < K; k += 16) {
        wmma::fragment<wmma::matrix_a, 16, 16, 16, __half, wmma::row_major> a[2];
#pragma unroll
        for (int mi = 0; mi < 2; mi++)
            wmma::load_matrix_sync(a[mi], sA + (size_t)(warp_m * 32 + mi * 16) * AS + k, AS);
#pragma unroll
        for (int f = 0; f < NFRAG; f++) {
            wmma::fragment<wmma::matrix_b, 16, 16, 16, __half, wmma::row_major> b;
            wmma::load_matrix_sync(b, sW + (size_t)k * WS + warp_n * NSPAN + f * 16, WS);
#pragma unroll
            for (int mi = 0; mi < 2; mi++) wmma::mma_sync(c[mi][f], a[mi], b, c[mi][f]);
        }
        if (warp_n == 0) {
            wmma::fragment<wmma::matrix_b, 16, 16, 16, __half, wmma::row_major> be;
            wmma::load_matrix_sync(be, sW + (size_t)k * WS + NC, WS);
#pragma unroll
            for (int mi = 0; mi < 2; mi++) wmma::mma_sync(ce[mi], a[mi], be, ce[mi]);
        }
    }
    __syncthreads();

#pragma unroll
    for (int mi = 0; mi < 2; mi++) {
        int rbase = (warp_m * 32 + mi * 16) * NCP;
#pragma unroll
        for (int f = 0; f < NFRAG; f++)
            wmma::store_matrix_sync(ep + rbase + warp_n * NSPAN + f * 16,
                                    c[mi][f], NCP, wmma::mem_row_major);
        if (warp_n == 0)
            wmma::store_matrix_sync(ep + rbase + NC, ce[mi], NCP, wmma::mem_row_major);
    }
    __syncthreads();

    {
        constexpr int RPT = NC / 4;
        int j = tid % NC;
        int r0 = (tid / NC) * RPT;
        for (int r = r0; r < r0 + RPT; r++) {
            int row = m0 + r;
            if (row < n) feat[(size_t)row * NC + j] = __float2half_rn(ep[r * NCP + j]);
        }
    }
    {
        int e0 = tid * 4;
#pragma unroll
        for (int e = e0; e < e0 + 4; e++) {
            int r = e >> 4, cc = e & 15;
            int row = m0 + r;
            if (row < n) {
                float v = ep[r * NCP + NC + cc];
                if (cc < 8) el[row * H + cc] = v;
                else        er[row * H + (cc - 8)] = v;
            }
        }
    }
}

#define SMEM_G(K, NC) (((K)*((NC)+16+8) + 64*((K)+8)) * 2 > 64*((NC)+16)*4 ? \
                       ((K)*((NC)+16+8) + 64*((K)+8)) * 2 : 64*((NC)+16)*4)
#define SMEM1 SMEM_G(INF_, C1)
#define SMEM2 SMEM_G(C1, C2)

// ---------------- fused per-node softmax + aggregate (single pass) ----------
template<int DT, bool ELU, bool FINAL>
__global__ void node_aggregate(const __half* __restrict__ feat,
                               const float* __restrict__ el,
                               const float* __restrict__ er,
                               const float* __restrict__ bias,
                               void* __restrict__ outp)
{
    int d = blockIdx.x * (blockDim.x >> 5) + (threadIdx.x >> 5);
    if (d >= NN) return;
    int lane = threadIdx.x & 31;
    int head = lane >> 2;
    constexpr int V = DT / 32;
    constexpr int NH2 = V / 2;

    int beg = g_rowstart[d], end = g_rowstart[d + 1];

    float sum = 0.f;
    float acc[V];
#pragma unroll
    for (int k = 0; k < V; k++) acc[k] = 0.f;

    float erv = (beg < end) ? er[d * H + head] : 0.f;

    for (int i = beg; i < end; i += 4) {
        int4 sv = *(const int4*)(g_csr + i);
        int s0 = sv.x, s1 = sv.y, s2 = sv.z, s3 = sv.w;
        float l0 = el[s0 * H + head];
        float l1 = el[s1 * H + head];
        float l2 = el[s2 * H + head];
        float l3 = el[s3 * H + head];
        __half2 v0[NH2], v1[NH2], v2[NH2], v3[NH2];
        if (V == 8) {
            *(uint4*)v0 = *(const uint4*)((const __half2*)(feat + (size_t)s0 * DT) + lane * NH2);
            *(uint4*)v1 = *(const uint4*)((const __half2*)(feat + (size_t)s1 * DT) + lane * NH2);
            *(uint4*)v2 = *(const uint4*)((const __half2*)(feat + (size_t)s2 * DT) + lane * NH2);
            *(uint4*)v3 = *(const uint4*)((const __half2*)(feat + (size_t)s3 * DT) + lane * NH2);
        } else {
            *(uint2*)v0 = *(const uint2*)((const __half2*)(feat + (size_t)s0 * DT) + lane * NH2);
            *(uint2*)v1 = *(const uint2*)((const __half2*)(feat + (size_t)s1 * DT) + lane * NH2);
            *(uint2*)v2 = *(const uint2*)((const __half2*)(feat + (size_t)s2 * DT) + lane * NH2);
            *(uint2*)v3 = *(const uint2*)((const __half2*)(feat + (size_t)s3 * DT) + lane * NH2);
        }
        l0 += erv; l1 += erv; l2 += erv; l3 += erv;
        l0 = l0 > 0.f ? l0 : 0.2f * l0;
        l1 = l1 > 0.f ? l1 : 0.2f * l1;
        l2 = l2 > 0.f ? l2 : 0.2f * l2;
        l3 = l3 > 0.f ? l3 : 0.2f * l3;
        float w0 = __expf(l0), w1 = __expf(l1), w2 = __expf(l2), w3 = __expf(l3);
        sum += (w0 + w1) + (w2 + w3);
#pragma unroll
        for (int k = 0; k < NH2; k++) {
            float2 a0 = __half22float2(v0[k]);
            float2 a1 = __half22float2(v1[k]);
            float2 a2 = __half22float2(v2[k]);
            float2 a3 = __half22float2(v3[k]);
            acc[k*2+0] += w0*a0.x + w1*a1.x + w2*a2.x + w3*a3.x;
            acc[k*2+1] += w0*a0.y + w1*a1.y + w2*a2.y + w3*a3.y;
        }
    }

    float inv = (beg < end) ? 1.f / sum : 0.f;

    float vals[V];
#pragma unroll
    for (int k = 0; k < V; k++) {
        float v = acc[k] * inv + bias[lane * V + k];
        vals[k] = ELU ? (v > 0.f ? v : expm1f(v)) : v;
    }

    if (!FINAL) {
        __half2 hv[NH2];
#pragma unroll
        for (int k = 0; k < NH2; k++)
            hv[k] = __floats2half2_rn(vals[k*2+0], vals[k*2+1]);
        __half* op = (__half*)outp + (size_t)d * DT + lane * V;
        if (V == 8) *(uint4*)op = *(uint4*)hv;
        else        *(uint2*)op = *(uint2*)hv;
    } else {
#pragma unroll
        for (int off = 4; off <= 16; off <<= 1) {
#pragma unroll
            for (int k = 0; k < V; k++)
                vals[k] += __shfl_xor_sync(0xffffffffu, vals[k], off);
        }
        if (lane < 4) {
            float4 o = make_float4(vals[0] * 0.125f, vals[1] * 0.125f,
                                   vals[2] * 0.125f, vals[3] * 0.125f);
            ((float4*)((float*)outp + (size_t)d * OUTD))[lane] = o;
        }
    }
}

// ---------------- launch ----------------------------------------------------
extern "C" void kernel_launch(void* const* d_in, const int* in_sizes, int n_in,
                              void* d_out, int out_size)
{
    const float* x   = (const float*)d_in[0];
    const float* W1  = (const float*)d_in[1];
    const float* al1 = (const float*)d_in[2];
    const float* ar1 = (const float*)d_in[3];
    const float* b1  = (const float*)d_in[4];
    const float* W2  = (const float*)d_in[5];
    const float* al2 = (const float*)d_in[6];
    const float* ar2 = (const float*)d_in[7];
    const float* b2  = (const float*)d_in[8];
    const int*   src = (const int*)d_in[9];
    const int*   dst = (const int*)d_in[10];
    float* out = (float*)d_out;

    __half *x16, *W1e, *W2e, *feat1, *agg1, *feat2;
    float *el, *er;
    cudaGetSymbolAddress((void**)&x16,   g_x16);
    cudaGetSymbolAddress((void**)&W1e,   g_W1e);
    cudaGetSymbolAddress((void**)&W2e,   g_W2e);
    cudaGetSymbolAddress((void**)&feat1, g_feat1);
    cudaGetSymbolAddress((void**)&agg1,  g_agg1);
    cudaGetSymbolAddress((void**)&feat2, g_feat2);
    cudaGetSymbolAddress((void**)&el,    g_el);
    cudaGetSymbolAddress((void**)&er,    g_er);

    static bool attrDone = false;
    if (!attrDone) {
        cudaFuncSetAttribute((const void*)gemm_att_wmma<INF_, C1, HIDD>,
                             cudaFuncAttributeMaxDynamicSharedMemorySize, SMEM1);
        cudaFuncSetAttribute((const void*)gemm_att_wmma<C1, C2, OUTD>,
                             cudaFuncAttributeMaxDynamicSharedMemorySize, SMEM2);
        cudaFuncSetAttribute((const void*)k_scan,
                             cudaFuncAttributeMaxDynamicSharedMemorySize, SCAN_SMEM);
        attrDone = true;
    }

    const int eBlocks    = (EE + 255) / 256;
    const int gemmBlocks = NNP / 64;
    const int nodeBlocks = (NN + 7) / 8;

    // 1: converts + extended W + cnt zero + csr/el dummies
    k_convert<<<(NN*INF_ + 255)/256, 256>>>(x, W1, al1, ar1, W2, al2, ar2);
    // 2: dst histogram
    k_hist<<<eBlocks, 256>>>(dst);
    // 3: layer-1 GEMM (needs convert only)
    gemm_att_wmma<INF_, C1, HIDD><<<gemmBlocks, 256, SMEM1>>>(x16, W1e, feat1, el, er, NN);
    // 4: O(1)-barrier scan  <-- profiled slot
    k_scan<<<1, SCAN_T, SCAN_SMEM>>>();
    // 5: scatter
    k_scatter<<<eBlocks, 256>>>(src, dst);
    // 6: layer-1 aggregate
    node_aggregate<C1, true, false><<<nodeBlocks, 256>>>(feat1, el, er, b1, agg1);
    // 7: layer-2 GEMM
    gemm_att_wmma<C1, C2, OUTD><<<gemmBlocks, 256, SMEM2>>>(agg1, W2e, feat2, el, er, NN);
    // 8: layer-2 aggregate + head-mean
    node_aggregate<C2, false, true><<<nodeBlocks, 256>>>(feat2, el, er, b2, out);
}

// round 16
// speedup vs baseline: 1.9172x; 1.0188x over previous
#include <cuda_runtime.h>
#include <cuda_fp16.h>
#include <mma.h>
#include <math.h>

using namespace nvcuda;

#define NN   50000
#define NNP  50048           // padded to multiple of 64
#define EE   800000
#define CSRP (EE + 4*NN)     // CSR capacity with per-row pad-to-4
#define INF_ 128
#define H    8
#define HIDD 32
#define OUTD 16
#define C1   (H*HIDD)   // 256
#define C2   (H*OUTD)   // 128
#define NCP1 (C1 + 16)  // 272
#define NCP2 (C2 + 16)  // 144

#define SCAN_T  1024
#define SCAN_CH 49                    // 1024*49 = 50176 >= NN
#define SCAN_NP (SCAN_T * SCAN_CH)
#define SCAN_SMEM ((SCAN_NP + SCAN_T) * 4)

// ---------------- scratch (device globals, zero-initialized) ----------------
__device__ __half g_x16  [(size_t)NNP * INF_];
__device__ __half g_W1e  [INF_ * NCP1];        // W1 | wl1(8) | wr1(8)
__device__ __half g_W2e  [C1 * NCP2];          // W2 | wl2(8) | wr2(8)
__device__ __half g_feat1[(size_t)NNP * C1];   // row NN stays zero (dummy)
__device__ __half g_agg1 [(size_t)NNP * C1];
__device__ __half g_feat2[(size_t)NNP * C2];
__device__ float  g_el   [(NN + 1) * H];       // el[NN][*] = -1e30 (dummy)
__device__ float  g_er   [NN * H];
__device__ int    g_csr  [CSRP];
__device__ int    g_rowstart[NN + 1];
__device__ int    g_cnt  [NN];

// ------- merged: converts + extended-W build + zero cnt + csr/el dummies ----
__global__ void k_convert(const float* __restrict__ x,
                          const float* __restrict__ W1, const float* __restrict__ al1,
                          const float* __restrict__ ar1,
                          const float* __restrict__ W2, const float* __restrict__ al2,
                          const float* __restrict__ ar2) {
    int i = blockIdx.x * blockDim.x + threadIdx.x;
    if (i < NN * INF_) g_x16[i] = __float2half_rn(x[i]);
    if (i < INF_ * C1) {
        int k = i >> 8, j = i & 255;
        g_W1e[k * NCP1 + j] = __float2half_rn(W1[i]);
    }
    if (i < C1 * C2) {
        int k = i >> 7, j = i & 127;
        g_W2e[k * NCP2 + j] = __float2half_rn(W2[i]);
    }
    if (i < INF_ * H) {            // wl1/wr1: [128][8]
        int k = i >> 3, h = i & 7;
        float sl = 0.f, sr = 0.f;
#pragma unroll
        for (int d = 0; d < HIDD; d++) {
            float w = W1[k * C1 + h * HIDD + d];
            sl += w * al1[h * HIDD + d];
            sr += w * ar1[h * HIDD + d];
        }
        g_W1e[k * NCP1 + C1 + h]     = __float2half_rn(sl);
        g_W1e[k * NCP1 + C1 + 8 + h] = __float2half_rn(sr);
    }
    if (i < C1 * H) {              // wl2/wr2: [256][8]
        int k = i >> 3, h = i & 7;
        float sl = 0.f, sr = 0.f;
#pragma unroll
        for (int d = 0; d < OUTD; d++) {
            float w = W2[k * C2 + h * OUTD + d];
            sl += w * al2[h * OUTD + d];
            sr += w * ar2[h * OUTD + d];
        }
        g_W2e[k * NCP2 + C2 + h]     = __float2half_rn(sl);
        g_W2e[k * NCP2 + C2 + 8 + h] = __float2half_rn(sr);
    }
    if (i < NN)   g_cnt[i] = 0;
    if (i < CSRP) g_csr[i] = NN;              // dummy src (zero weight)
    if (i < H)    g_el[NN * H + i] = -1e30f;  // dummy logit -> exp = 0
}

__global__ void k_hist(const int* __restrict__ dst) {
    int e = blockIdx.x * blockDim.x + threadIdx.x;
    if (e < EE) atomicAdd(&g_cnt[dst[e]], 1);
}

// ---- single-block scan, O(1) barriers: smem-buffered, coalesced both ways ---
__global__ void k_scan() {
    extern __shared__ int S[];            // [SCAN_NP] values + [SCAN_T] totals
    __shared__ int wsum[32];
    int* T = S + SCAN_NP;
    int t = threadIdx.x;
    int lane = t & 31, w = t >> 5;

#pragma unroll
    for (int j = 0; j < SCAN_CH; j++) {
        int idx = j * SCAN_T + t;
        int c = (idx < NN) ? g_cnt[idx] : 0;
        S[idx] = (c + 3) & ~3;
    }
    __syncthreads();

    int base = t * SCAN_CH;
    int run = 0;
#pragma unroll
    for (int i = 0; i < SCAN_CH; i++) {
        int v = S[base + i];
        S[base + i] = run;
        run += v;
    }
    T[t] = run;
    __syncthreads();

    int v = T[t], inc = v;
#pragma unroll
    for (int o = 1; o < 32; o <<= 1) {
        int u = __shfl_up_sync(0xffffffffu, inc, o);
        if (lane >= o) inc += u;
    }
    if (lane == 31) wsum[w] = inc;
    __syncthreads();
    if (w == 0) {
        int s = wsum[lane];
#pragma unroll
        for (int o = 1; o < 32; o <<= 1) {
            int u = __shfl_up_sync(0xffffffffu, s, o);
            if (lane >= o) s += u;
        }
        wsum[lane] = s;
    }
    __syncthreads();
    int chunk_off = inc - v + (w > 0 ? wsum[w - 1] : 0);
    T[t] = chunk_off;
    __syncthreads();

#pragma unroll
    for (int j = 0; j < SCAN_CH; j++) {
        int idx = j * SCAN_T + t;
        if (idx < NN) {
            int excl = S[idx] + T[idx / SCAN_CH];
            g_rowstart[idx] = excl;
            g_cnt[idx] = excl;
        }
    }
    if (t == SCAN_T - 1) g_rowstart[NN] = chunk_off + run;
}

__global__ void k_scatter(const int* __restrict__ src, const int* __restrict__ dst) {
    int e = blockIdx.x * blockDim.x + threadIdx.x;
    if (e >= EE) return;
    int p = atomicAdd(&g_cnt[dst[e]], 1);
    g_csr[p] = src[e];
}

// ---------- N-split smem-tiled tensor-core GEMM, el/er as extra columns -----
// Block = 64 rows x NCB cols, NCB = NC/NSPLIT; blockIdx.y picks the N-slice.
// W-slice (+16 extra cols on y==0) and A tile staged in smem; 8 warps in
// 2m x 4n layout, NSPAN = NCB/4. y==0, warp_n==0 also computes el/er columns.
template<int K, int NC, int NSPLIT>
__global__ __launch_bounds__(256, 3)
void gemm_att_wmma(const __half* __restrict__ A, const __half* __restrict__ We,
                   __half* __restrict__ feat, float* __restrict__ el,
                   float* __restrict__ er, int n)
{
    constexpr int NCB  = NC / NSPLIT;     // 128 both layers
    constexpr int NCPB = NCB + 16;        // 144
    constexpr int NCPF = NC + 16;         // full We row stride
    constexpr int WS = NCPB + 8;          // 152
    constexpr int AS = K + 8;
    extern __shared__ char smraw[];
    __half* sW = (__half*)smraw;                       // K * WS
    __half* sA = (__half*)smraw + (size_t)K * WS;      // 64 * AS
    float*  ep = (float*)smraw;                        // 64 * NCPB (reuse)

    constexpr int NSPAN = NCB / 4;        // 32
    constexpr int NFRAG = NSPAN / 16;     // 2

    int tid = threadIdx.x;
    int wid = tid >> 5;
    int warp_m = wid & 1;
    int warp_n = wid >> 1;
    int m0 = blockIdx.x * 64;
    int colbase = blockIdx.y * NCB;
    bool lead = (blockIdx.y == 0);

    // stage W slice
    {
        constexpr int G = NCB / 8;        // uint4 groups per row
        for (int idx = tid; idx < K * G; idx += 256) {
            int row = idx / G, g = idx % G;
            *(uint4*)(sW + (size_t)row * WS + g * 8) =
                *(const uint4*)(We + (size_t)row * NCPF + colbase + g * 8);
        }
        if (lead) {   // extra 16 el/er cols -> smem cols [NCB, NCB+16)
            for (int idx = tid; idx < K * 2; idx += 256) {
                int row = idx >> 1, g = idx & 1;
                *(uint4*)(sW + (size_t)row * WS + NCB + g * 8) =
                    *(const uint4*)(We + (size_t)row * NCPF + NC + g * 8);
            }
        }
    }
    // stage A tile
    {
        constexpr int G = K / 8;
        const uint4* ag = (const uint4*)(A + (size_t)m0 * K);
        for (int idx = tid; idx < 64 * G; idx += 256) {
            int row = idx / G, g = idx % G;
            *(uint4*)(sA + (size_t)row * AS + g * 8) = ag[(size_t)row * G + g];
        }
    }
    __syncthreads();

    wmma::fragment<wmma::accumulator, 16, 16, 16, float> c[2][NFRAG], ce[2];
#pragma unroll
    for (int mi = 0; mi < 2; mi++) {
#pragma unroll
        for (int f = 0; f < NFRAG; f++) wmma::fill_fragment(c[mi][f], 0.f);
        wmma::fill_fragment(ce[mi], 0.f);
    }

    bool do_extra = lead && (warp_n == 0);
    for (int k = 0; k < K; k += 16) {
        wmma::fragment<wmma::matrix_a, 16, 16, 16, __half, wmma::row_major> a[2];
#pragma unroll
        for (int mi = 0; mi < 2; mi++)
            wmma::load_matrix_sync(a[mi], sA + (size_t)(warp_m * 32 + mi * 16) * AS + k, AS);
#pragma unroll
        for (int f = 0; f < NFRAG; f++) {
            wmma::fragment<wmma::matrix_b, 16, 16, 16, __half, wmma::row_major> b;
            wmma::load_matrix_sync(b, sW + (size_t)k * WS + warp_n * NSPAN + f * 16, WS);
#pragma unroll
            for (int mi = 0; mi < 2; mi++) wmma::mma_sync(c[mi][f], a[mi], b, c[mi][f]);
        }
        if (do_extra) {
            wmma::fragment<wmma::matrix_b, 16, 16, 16, __half, wmma::row_major> be;
            wmma::load_matrix_sync(be, sW + (size_t)k * WS + NCB, WS);
#pragma unroll
            for (int mi = 0; mi < 2; mi++) wmma::mma_sync(ce[mi], a[mi], be, ce[mi]);
        }
    }
    __syncthreads();   // fragment reads done before smem reuse

#pragma unroll
    for (int mi = 0; mi < 2; mi++) {
        int rbase = (warp_m * 32 + mi * 16) * NCPB;
#pragma unroll
        for (int f = 0; f < NFRAG; f++)
            wmma::store_matrix_sync(ep + rbase + warp_n * NSPAN + f * 16,
                                    c[mi][f], NCPB, wmma::mem_row_major);
        if (do_extra)
            wmma::store_matrix_sync(ep + rbase + NCB, ce[mi], NCPB, wmma::mem_row_major);
    }
    __syncthreads();

    // feat: 64 rows x NCB cols; thread j = tid % NCB handles 64*NCB/256 rows
    {
        constexpr int RPT = 64 * NCB / (256 * NCB / NCB) / (256 / NCB); // rows per thread
        int j = tid % NCB;
        int r0 = (tid / NCB) * (64 / (256 / NCB));
        constexpr int RSPAN = 64 / (256 / NCB);     // 32 for NCB=128
        (void)RPT;
        for (int r = r0; r < r0 + RSPAN; r++) {
            int row = m0 + r;
            if (row < n) feat[(size_t)row * NC + colbase + j] =
                __float2half_rn(ep[r * NCPB + j]);
        }
    }
    // el/er: lead block only; 64 rows x 16 cols, 4 per thread
    if (lead) {
        int e0 = tid * 4;
#pragma unroll
        for (int e = e0; e < e0 + 4; e++) {
            int r = e >> 4, cc = e & 15;
            int row = m0 + r;
            if (row < n) {
                float v = ep[r * NCPB + NCB + cc];
                if (cc < 8) el[row * H + cc] = v;
                else        er[row * H + (cc - 8)] = v;
            }
        }
    }
}

// smem: max(staging, epilogue)
#define SMEM_G(K) (((K)*152 + 64*((K)+8)) * 2 > 64*144*4 ? \
                   ((K)*152 + 64*((K)+8)) * 2 : 64*144*4)
#define SMEM1 SMEM_G(INF_)     // 56320
#define SMEM2 SMEM_G(C1)       // 111616

// ---------------- fused per-node softmax + aggregate (single pass) ----------
template<int DT, bool ELU, bool FINAL>
__global__ void node_aggregate(const __half* __restrict__ feat,
                               const float* __restrict__ el,
                               const float* __restrict__ er,
                               const float* __restrict__ bias,
                               void* __restrict__ outp)
{
    int d = blockIdx.x * (blockDim.x >> 5) + (threadIdx.x >> 5);
    if (d >= NN) return;
    int lane = threadIdx.x & 31;
    int head = lane >> 2;
    constexpr int V = DT / 32;
    constexpr int NH2 = V / 2;

    int beg = g_rowstart[d], end = g_rowstart[d + 1];

    float sum = 0.f;
    float acc[V];
#pragma unroll
    for (int k = 0; k < V; k++) acc[k] = 0.f;

    float erv = (beg < end) ? er[d * H + head] : 0.f;

    for (int i = beg; i < end; i += 4) {
        int4 sv = *(const int4*)(g_csr + i);
        int s0 = sv.x, s1 = sv.y, s2 = sv.z, s3 = sv.w;
        float l0 = el[s0 * H + head];
        float l1 = el[s1 * H + head];
        float l2 = el[s2 * H + head];
        float l3 = el[s3 * H + head];
        __half2 v0[NH2], v1[NH2], v2[NH2], v3[NH2];
        if (V == 8) {
            *(uint4*)v0 = *(const uint4*)((const __half2*)(feat + (size_t)s0 * DT) + lane * NH2);
            *(uint4*)v1 = *(const uint4*)((const __half2*)(feat + (size_t)s1 * DT) + lane * NH2);
            *(uint4*)v2 = *(const uint4*)((const __half2*)(feat + (size_t)s2 * DT) + lane * NH2);
            *(uint4*)v3 = *(const uint4*)((const __half2*)(feat + (size_t)s3 * DT) + lane * NH2);
        } else {
            *(uint2*)v0 = *(const uint2*)((const __half2*)(feat + (size_t)s0 * DT) + lane * NH2);
            *(uint2*)v1 = *(const uint2*)((const __half2*)(feat + (size_t)s1 * DT) + lane * NH2);
            *(uint2*)v2 = *(const uint2*)((const __half2*)(feat + (size_t)s2 * DT) + lane * NH2);
            *(uint2*)v3 = *(const uint2*)((const __half2*)(feat + (size_t)s3 * DT) + lane * NH2);
        }
        l0 += erv; l1 += erv; l2 += erv; l3 += erv;
        l0 = l0 > 0.f ? l0 : 0.2f * l0;
        l1 = l1 > 0.f ? l1 : 0.2f * l1;
        l2 = l2 > 0.f ? l2 : 0.2f * l2;
        l3 = l3 > 0.f ? l3 : 0.2f * l3;
        float w0 = __expf(l0), w1 = __expf(l1), w2 = __expf(l2), w3 = __expf(l3);
        sum += (w0 + w1) + (w2 + w3);
#pragma unroll
        for (int k = 0; k < NH2; k++) {
            float2 a0 = __half22float2(v0[k]);
            float2 a1 = __half22float2(v1[k]);
            float2 a2 = __half22float2(v2[k]);
            float2 a3 = __half22float2(v3[k]);
            acc[k*2+0] += w0*a0.x + w1*a1.x + w2*a2.x + w3*a3.x;
            acc[k*2+1] += w0*a0.y + w1*a1.y + w2*a2.y + w3*a3.y;
        }
    }

    float inv = (beg < end) ? 1.f / sum : 0.f;

    float vals[V];
#pragma unroll
    for (int k = 0; k < V; k++) {
        float v = acc[k] * inv + bias[lane * V + k];
        vals[k] = ELU ? (v > 0.f ? v : expm1f(v)) : v;
    }

    if (!FINAL) {
        __half2 hv[NH2];
#pragma unroll
        for (int k = 0; k < NH2; k++)
            hv[k] = __floats2half2_rn(vals[k*2+0], vals[k*2+1]);
        __half* op = (__half*)outp + (size_t)d * DT + lane * V;
        if (V == 8) *(uint4*)op = *(uint4*)hv;
        else        *(uint2*)op = *(uint2*)hv;
    } else {
#pragma unroll
        for (int off = 4; off <= 16; off <<= 1) {
#pragma unroll
            for (int k = 0; k < V; k++)
                vals[k] += __shfl_xor_sync(0xffffffffu, vals[k], off);
        }
        if (lane < 4) {
            float4 o = make_float4(vals[0] * 0.125f, vals[1] * 0.125f,
                                   vals[2] * 0.125f, vals[3] * 0.125f);
            ((float4*)((float*)outp + (size_t)d * OUTD))[lane] = o;
        }
    }
}

// ---------------- launch ----------------------------------------------------
extern "C" void kernel_launch(void* const* d_in, const int* in_sizes, int n_in,
                              void* d_out, int out_size)
{
    const float* x   = (const float*)d_in[0];
    const float* W1  = (const float*)d_in[1];
    const float* al1 = (const float*)d_in[2];
    const float* ar1 = (const float*)d_in[3];
    const float* b1  = (const float*)d_in[4];
    const float* W2  = (const float*)d_in[5];
    const float* al2 = (const float*)d_in[6];
    const float* ar2 = (const float*)d_in[7];
    const float* b2  = (const float*)d_in[8];
    const int*   src = (const int*)d_in[9];
    const int*   dst = (const int*)d_in[10];
    float* out = (float*)d_out;

    __half *x16, *W1e, *W2e, *feat1, *agg1, *feat2;
    float *el, *er;
    cudaGetSymbolAddress((void**)&x16,   g_x16);
    cudaGetSymbolAddress((void**)&W1e,   g_W1e);
    cudaGetSymbolAddress((void**)&W2e,   g_W2e);
    cudaGetSymbolAddress((void**)&feat1, g_feat1);
    cudaGetSymbolAddress((void**)&agg1,  g_agg1);
    cudaGetSymbolAddress((void**)&feat2, g_feat2);
    cudaGetSymbolAddress((void**)&el,    g_el);
    cudaGetSymbolAddress((void**)&er,    g_er);

    static bool attrDone = false;
    if (!attrDone) {
        cudaFuncSetAttribute((const void*)gemm_att_wmma<INF_, C1, 2>,
                             cudaFuncAttributeMaxDynamicSharedMemorySize, SMEM1);
        cudaFuncSetAttribute((const void*)gemm_att_wmma<C1, C2, 1>,
                             cudaFuncAttributeMaxDynamicSharedMemorySize, SMEM2);
        cudaFuncSetAttribute((const void*)k_scan,
                             cudaFuncAttributeMaxDynamicSharedMemorySize, SCAN_SMEM);
        attrDone = true;
    }

    const int eBlocks    = (EE + 255) / 256;
    const int gemmBlocks = NNP / 64;
    const int nodeBlocks = (NN + 7) / 8;

    // 1: converts + extended W + cnt zero + csr/el dummies
    k_convert<<<(NN*INF_ + 255)/256, 256>>>(x, W1, al1, ar1, W2, al2, ar2);
    // 2: dst histogram
    k_hist<<<eBlocks, 256>>>(dst);
    // 3: scan
    k_scan<<<1, SCAN_T, SCAN_SMEM>>>();
    // 4: layer-1 GEMM (N-split x2)  <-- profiled slot
    gemm_att_wmma<INF_, C1, 2><<<dim3(gemmBlocks, 2), 256, SMEM1>>>(
        x16, W1e, feat1, el, er, NN);
    // 5: scatter
    k_scatter<<<eBlocks, 256>>>(src, dst);
    // 6: layer-1 aggregate
    node_aggregate<C1, true, false><<<nodeBlocks, 256>>>(feat1, el, er, b1, agg1);
    // 7: layer-2 GEMM
    gemm_att_wmma<C1, C2, 1><<<dim3(gemmBlocks, 1), 256, SMEM2>>>(
        agg1, W2e, feat2, el, er, NN);
    // 8: layer-2 aggregate + head-mean
    node_aggregate<C2, false, true><<<nodeBlocks, 256>>>(feat2, el, er, b2, out);
}